// round 5
// baseline (speedup 1.0000x reference)
#include <cuda_runtime.h>
#include <math.h>

// ---------------------------------------------------------------------------
//   x: (B=512, C=1024, 7, 7) -> N = 49 tokens/window, M = B*N = 25088
//   Q = (xt @ Wq^T + bq) * D^-0.5 ; KV = xt @ Wkv^T + bkv
//   attn = mix(softmax, relu^2)(q k^T + rpb) ; o = attn v ; y = o @ Wproj^T + b
// ---------------------------------------------------------------------------
#define BD   512
#define CD   1024
#define NTOK 49
#define HH   8
#define DD   128
#define MM   (BD * NTOK)          // 25088
#define KK   1024

// Device scratch (allocation-free rule: __device__ globals)
__device__ float g_xt [MM * CD];          // (M, C)   xt, tf32-rounded
__device__ float g_qkv[MM * 3 * CD];      // (M, 3C)  [q | k | v]  fp32
__device__ float g_o1 [MM * CD];          // (M, C)   attn out, tf32-rounded
__device__ float g_o2 [MM * CD];          // (M, C)   proj out fp32
__device__ float g_wq [CD * KK];          // tf32-rounded weights
__device__ float g_wkv[2 * CD * KK];
__device__ float g_wp [CD * KK];

// ---------------------------------------------------------------------------
// Helpers
// ---------------------------------------------------------------------------
__device__ __forceinline__ unsigned f2tf(float x) {
    unsigned r;
    asm("cvt.rna.tf32.f32 %0, %1;" : "=r"(r) : "f"(x));
    return r;
}

__device__ __forceinline__ void mma8(float* c, const unsigned* a, const unsigned* b) {
    asm volatile(
        "mma.sync.aligned.m16n8k8.row.col.f32.tf32.tf32.f32 "
        "{%0,%1,%2,%3}, {%4,%5,%6,%7}, {%8,%9}, {%0,%1,%2,%3};"
        : "+f"(c[0]), "+f"(c[1]), "+f"(c[2]), "+f"(c[3])
        : "r"(a[0]), "r"(a[1]), "r"(a[2]), "r"(a[3]), "r"(b[0]), "r"(b[1]));
}

__device__ __forceinline__ void cpa16(unsigned dst, const float* src) {
    asm volatile("cp.async.cg.shared.global [%0], [%1], 16;\n" :: "r"(dst), "l"(src));
}
__device__ __forceinline__ void cpa_commit() {
    asm volatile("cp.async.commit_group;\n");
}
__device__ __forceinline__ void cpa_wait1() {
    asm volatile("cp.async.wait_group 1;\n");
}

// ---------------------------------------------------------------------------
// Kernel 0: elementwise f32 -> tf32(rna) copy (weights prep)
// ---------------------------------------------------------------------------
__global__ __launch_bounds__(256) void cvt_tf32(const float* __restrict__ src,
                                                float* __restrict__ dst, int n4) {
    int i = blockIdx.x * 256 + threadIdx.x;
    if (i < n4) {
        float4 v = ((const float4*)src)[i];
        uint4 u = { f2tf(v.x), f2tf(v.y), f2tf(v.z), f2tf(v.w) };
        ((uint4*)dst)[i] = u;
    }
}

// ---------------------------------------------------------------------------
// Kernel 1: x (B, C, N) -> xt (M, C), tf32-rounded
// ---------------------------------------------------------------------------
__global__ __launch_bounds__(256) void transpose_in(const float* __restrict__ x) {
    __shared__ float t[32][51];
    int b  = blockIdx.x;
    int c0 = blockIdx.y * 32;
    const float* xp = x + (size_t)b * CD * NTOK + (size_t)c0 * NTOK;
    for (int idx = threadIdx.x; idx < 32 * NTOK; idx += 256) {
        int c = idx / NTOK, n = idx - c * NTOK;
        t[c][n] = xp[c * NTOK + n];
    }
    __syncthreads();
    for (int idx = threadIdx.x; idx < 32 * NTOK; idx += 256) {
        int n = idx >> 5, c = idx & 31;
        ((unsigned*)g_xt)[(size_t)(b * NTOK + n) * CD + c0 + c] = f2tf(t[c][n]);
    }
}

// ---------------------------------------------------------------------------
// Kernel 2: GEMM  C[m, colOff+n] = A[m,:] . W[n,:] + bias[n]
//   A, W already tf32-rounded fp32 bits. 128x128x32 tile, 3-buffer cp.async,
//   8 warps (2x4), warp tile 64x32, mma m16n8k8 tf32.
//   GRID: blockIdx.x = n-tile (few), blockIdx.y = m-tile (196) so that a
//   wave of CTAs shares the A working set in L2 (A read ~once from DRAM).
// ---------------------------------------------------------------------------
#define BM 128
#define BN 128
#define BK 32
#define GP 36                       // smem pitch (conflict-free frag loads)
#define TILE_F (BM * GP)            // floats per A (or B) tile
#define STG_F  (2 * TILE_F)         // floats per stage
#define NKT (KK / BK)               // 32

__global__ __launch_bounds__(256) void gemm_tf32(
    const float* __restrict__ A, const float* __restrict__ W,
    const float* __restrict__ bias, float* __restrict__ Co,
    int ldc, int colOff)
{
    extern __shared__ float dsm[];                 // 3 stages * 2 tiles * 128*36

    const int tid  = threadIdx.x;
    const int m0   = blockIdx.y * BM;              // m-tile on Y (196)
    const int n0   = blockIdx.x * BN;              // n-tile on X (8..16)
    const int lrow = tid >> 3;                     // 0..31
    const int lc4  = (tid & 7) * 4;                // 0..28 step 4

    const float* Ab = A + (size_t)m0 * KK + lrow * KK + lc4;
    const float* Wb = W + (size_t)n0 * KK + lrow * KK + lc4;

    // smem byte addresses for this thread's cp.async destinations
    unsigned smBase = (unsigned)__cvta_generic_to_shared(dsm);
    unsigned aDst = smBase + (lrow * GP + lc4) * 4;
    unsigned bDst = aDst + TILE_F * 4;

    const int warp = tid >> 5, lane = tid & 31;
    const int wm = warp >> 2, wn = warp & 3;       // 2 x 4
    const int g = lane >> 2, t4 = lane & 3;

    float acc[4][4][4];
#pragma unroll
    for (int mi = 0; mi < 4; mi++)
#pragma unroll
        for (int ni = 0; ni < 4; ni++)
#pragma unroll
            for (int q = 0; q < 4; q++) acc[mi][ni][q] = 0.f;

    // prologue: stages 0, 1
#pragma unroll
    for (int s = 0; s < 2; s++) {
        unsigned off = s * STG_F * 4;
        const float* ap = Ab + s * BK;
        const float* wp = Wb + s * BK;
#pragma unroll
        for (int i = 0; i < 4; i++) {
            cpa16(aDst + off + i * 32 * GP * 4, ap + (size_t)i * 32 * KK);
            cpa16(bDst + off + i * 32 * GP * 4, wp + (size_t)i * 32 * KK);
        }
        cpa_commit();
    }

    int stage = 0;
    for (int kt = 0; kt < NKT; kt++) {
        cpa_wait1();                 // stage kt resident
        __syncthreads();

        // prefetch stage kt+2 into buffer (kt+2)%3
        if (kt + 2 < NKT) {
            int ps = stage + 2; if (ps >= 3) ps -= 3;
            unsigned off = ps * STG_F * 4;
            const float* ap = Ab + (kt + 2) * BK;
            const float* wp = Wb + (kt + 2) * BK;
#pragma unroll
            for (int i = 0; i < 4; i++) {
                cpa16(aDst + off + i * 32 * GP * 4, ap + (size_t)i * 32 * KK);
                cpa16(bDst + off + i * 32 * GP * 4, wp + (size_t)i * 32 * KK);
            }
        }
        cpa_commit();

        const unsigned* As = (const unsigned*)(dsm + stage * STG_F);
        const unsigned* Bs = As + TILE_F;

#pragma unroll
        for (int k8 = 0; k8 < 4; k8++) {
            unsigned af[4][4], bf[4][2];
#pragma unroll
            for (int mi = 0; mi < 4; mi++) {
                int rb = wm * 64 + mi * 16;
                af[mi][0] = As[(rb + g)     * GP + k8 * 8 + t4];
                af[mi][1] = As[(rb + g + 8) * GP + k8 * 8 + t4];
                af[mi][2] = As[(rb + g)     * GP + k8 * 8 + t4 + 4];
                af[mi][3] = As[(rb + g + 8) * GP + k8 * 8 + t4 + 4];
            }
#pragma unroll
            for (int ni = 0; ni < 4; ni++) {
                int nb = wn * 32 + ni * 8;
                bf[ni][0] = Bs[(nb + g) * GP + k8 * 8 + t4];
                bf[ni][1] = Bs[(nb + g) * GP + k8 * 8 + t4 + 4];
            }
#pragma unroll
            for (int mi = 0; mi < 4; mi++)
#pragma unroll
                for (int ni = 0; ni < 4; ni++)
                    mma8(acc[mi][ni], af[mi], bf[ni]);
        }
        stage++; if (stage >= 3) stage = 0;
    }

    // epilogue: + bias, fp32 out
#pragma unroll
    for (int mi = 0; mi < 4; mi++) {
#pragma unroll
        for (int ni = 0; ni < 4; ni++) {
            int row = m0 + wm * 64 + mi * 16 + g;
            int col = n0 + wn * 32 + ni * 8 + t4 * 2;
            float b0 = bias[col], b1 = bias[col + 1];
            float2 v0 = { acc[mi][ni][0] + b0, acc[mi][ni][1] + b1 };
            float2 v1 = { acc[mi][ni][2] + b0, acc[mi][ni][3] + b1 };
            *(float2*)&Co[(size_t)row       * ldc + colOff + col] = v0;
            *(float2*)&Co[(size_t)(row + 8) * ldc + colOff + col] = v1;
        }
    }
}

// ---------------------------------------------------------------------------
// Kernel 3: windowed attention per (b, h). 256 threads, 4096 blocks.
// ---------------------------------------------------------------------------
#define QKV_PITCH 132
#define ATTN_SMEM_FLOATS (3 * NTOK * QKV_PITCH + NTOK * NTOK + 169)
#define ATTN_SMEM_BYTES  (ATTN_SMEM_FLOATS * 4)

__global__ __launch_bounds__(256) void attn_kernel(const float* __restrict__ rpb_table,
                                                   const float* __restrict__ w_mix)
{
    extern __shared__ float sm[];
    float* qs = sm;
    float* ks = qs + NTOK * QKV_PITCH;
    float* vs = ks + NTOK * QKV_PITCH;
    float* ss = vs + NTOK * QKV_PITCH;
    float* rp = ss + NTOK * NTOK;

    int bh = blockIdx.x;
    int b = bh >> 3, h = bh & 7;
    int tid = threadIdx.x;

    // mix weights (uniform)
    float wa = w_mix[0], wb = w_mix[1];
    float wmx = fmaxf(wa, wb);
    float ea = __expf(wa - wmx), eb = __expf(wb - wmx);
    float wden = 1.f / (ea + eb);
    float w0 = ea * wden, w1 = eb * wden;

    const float scale = 0.08838834764831845f;      // 128^-0.5 (applied to q)

    size_t base = (size_t)(b * NTOK) * (3 * CD) + h * DD;
    for (int idx = tid; idx < NTOK * DD; idx += 256) {
        int i = idx >> 7, d = idx & 127;
        size_t r = base + (size_t)i * (3 * CD) + d;
        qs[i * QKV_PITCH + d] = g_qkv[r] * scale;
        ks[i * QKV_PITCH + d] = g_qkv[r + CD];
        vs[i * QKV_PITCH + d] = g_qkv[r + 2 * CD];
    }
    for (int idx = tid; idx < 169; idx += 256) rp[idx] = rpb_table[idx * HH + h];
    __syncthreads();

    // --- S = q k^T + rpb : 4x4 register tiles, 13x13 tile grid (169 threads)
    if (tid < 169) {
        int ti = tid / 13, tj = tid % 13;
        int ib = ti * 4, jb = tj * 4;
        int ri0 = (ib    < 49) ? ib     : 48;
        int ri1 = (ib + 1 < 49) ? ib + 1 : 48;
        int ri2 = (ib + 2 < 49) ? ib + 2 : 48;
        int ri3 = (ib + 3 < 49) ? ib + 3 : 48;
        int rj0 = (jb    < 49) ? jb     : 48;
        int rj1 = (jb + 1 < 49) ? jb + 1 : 48;
        int rj2 = (jb + 2 < 49) ? jb + 2 : 48;
        int rj3 = (jb + 3 < 49) ? jb + 3 : 48;
        const float4* q0 = (const float4*)(qs + ri0 * QKV_PITCH);
        const float4* q1 = (const float4*)(qs + ri1 * QKV_PITCH);
        const float4* q2 = (const float4*)(qs + ri2 * QKV_PITCH);
        const float4* q3 = (const float4*)(qs + ri3 * QKV_PITCH);
        const float4* k0 = (const float4*)(ks + rj0 * QKV_PITCH);
        const float4* k1 = (const float4*)(ks + rj1 * QKV_PITCH);
        const float4* k2 = (const float4*)(ks + rj2 * QKV_PITCH);
        const float4* k3 = (const float4*)(ks + rj3 * QKV_PITCH);

        float acc[4][4];
#pragma unroll
        for (int a = 0; a < 4; a++)
#pragma unroll
            for (int c = 0; c < 4; c++) acc[a][c] = 0.f;

#pragma unroll 4
        for (int t = 0; t < 32; t++) {
            float4 qr[4] = { q0[t], q1[t], q2[t], q3[t] };
            float4 kr[4] = { k0[t], k1[t], k2[t], k3[t] };
#pragma unroll
            for (int a = 0; a < 4; a++)
#pragma unroll
                for (int c = 0; c < 4; c++)
                    acc[a][c] += qr[a].x * kr[c].x + qr[a].y * kr[c].y
                               + qr[a].z * kr[c].z + qr[a].w * kr[c].w;
        }
#pragma unroll
        for (int a = 0; a < 4; a++) {
            int i = ib + a;
            if (i < 49) {
                int ri = i / 7, ci = i - 7 * ri;
#pragma unroll
                for (int c = 0; c < 4; c++) {
                    int j = jb + c;
                    if (j < 49) {
                        int rj = j / 7, cj = j - 7 * rj;
                        ss[i * 49 + j] = acc[a][c]
                                       + rp[(ri - rj + 6) * 13 + (ci - cj + 6)];
                    }
                }
            }
        }
    }
    __syncthreads();

    // --- row softmax + relu^2 mix (one warp per row)
    int warp = tid >> 5, lane = tid & 31;
    for (int r = warp; r < NTOK; r += 8) {
        float x0 = ss[r * NTOK + lane];
        bool v1 = (lane + 32) < NTOK;
        float x1 = v1 ? ss[r * NTOK + lane + 32] : -1e30f;
        float m = fmaxf(x0, x1);
#pragma unroll
        for (int o = 16; o > 0; o >>= 1) m = fmaxf(m, __shfl_xor_sync(0xffffffffu, m, o));
        float p0 = __expf(x0 - m);
        float p1 = v1 ? __expf(x1 - m) : 0.f;
        float s = p0 + p1;
#pragma unroll
        for (int o = 16; o > 0; o >>= 1) s += __shfl_xor_sync(0xffffffffu, s, o);
        float inv = 1.f / s;
        float r0 = fmaxf(x0, 0.f), r1 = fmaxf(x1, 0.f);
        ss[r * NTOK + lane] = w0 * p0 * inv + w1 * r0 * r0;
        if (v1) ss[r * NTOK + lane + 32] = w0 * p1 * inv + w1 * r1 * r1;
    }
    __syncthreads();

    // --- O = attn @ v : thread owns column d, 7-row chunks; v reused across rows
    {
        int d = tid & 127, half = tid >> 7;
        unsigned* o1u = (unsigned*)g_o1;
        size_t obase = (size_t)(b * NTOK) * CD + h * DD + d;
        for (int c = half; c < 7; c += 2) {
            float acc[7] = {0.f, 0.f, 0.f, 0.f, 0.f, 0.f, 0.f};
            const float* sbase = ss + (c * 7) * 49;
#pragma unroll 7
            for (int j = 0; j < 49; j++) {
                float vj = vs[j * QKV_PITCH + d];
#pragma unroll
                for (int ii = 0; ii < 7; ii++)
                    acc[ii] += sbase[ii * 49 + j] * vj;
            }
#pragma unroll
            for (int ii = 0; ii < 7; ii++)
                o1u[obase + (size_t)(c * 7 + ii) * CD] = f2tf(acc[ii]);
        }
    }
}

// ---------------------------------------------------------------------------
// Kernel 4: o2 (M, C) -> y (B, C, N)
// ---------------------------------------------------------------------------
__global__ __launch_bounds__(256) void transpose_out(float* __restrict__ y) {
    __shared__ float t[NTOK][33];
    int b  = blockIdx.x;
    int c0 = blockIdx.y * 32;
    for (int idx = threadIdx.x; idx < NTOK * 32; idx += 256) {
        int n = idx >> 5, c = idx & 31;
        t[n][c] = g_o2[(size_t)(b * NTOK + n) * CD + c0 + c];
    }
    __syncthreads();
    float* yp = y + (size_t)b * CD * NTOK + (size_t)c0 * NTOK;
    for (int idx = threadIdx.x; idx < 32 * NTOK; idx += 256) {
        int c = idx / NTOK, n = idx - c * NTOK;
        yp[c * NTOK + n] = t[n][c];
    }
}

// ---------------------------------------------------------------------------
// Launch
// ---------------------------------------------------------------------------
#define GEMM_SMEM (3 * STG_F * 4)          // 110592 bytes

extern "C" void kernel_launch(void* const* d_in, const int* in_sizes, int n_in,
                              void* d_out, int out_size)
{
    const float* x     = (const float*)d_in[0];
    const float* Wq    = (const float*)d_in[1];
    const float* bq    = (const float*)d_in[2];
    const float* Wkv   = (const float*)d_in[3];
    const float* bkv   = (const float*)d_in[4];
    const float* rpb   = (const float*)d_in[5];
    const float* wmix  = (const float*)d_in[6];
    const float* Wproj = (const float*)d_in[7];
    const float* bproj = (const float*)d_in[8];
    float* y = (float*)d_out;

    void *p_xt, *p_qkv, *p_o1, *p_o2, *p_wq, *p_wkv, *p_wp;
    cudaGetSymbolAddress(&p_xt,  g_xt);
    cudaGetSymbolAddress(&p_qkv, g_qkv);
    cudaGetSymbolAddress(&p_o1,  g_o1);
    cudaGetSymbolAddress(&p_o2,  g_o2);
    cudaGetSymbolAddress(&p_wq,  g_wq);
    cudaGetSymbolAddress(&p_wkv, g_wkv);
    cudaGetSymbolAddress(&p_wp,  g_wp);

    cudaFuncSetAttribute(attn_kernel, cudaFuncAttributeMaxDynamicSharedMemorySize,
                         ATTN_SMEM_BYTES);
    cudaFuncSetAttribute(gemm_tf32, cudaFuncAttributeMaxDynamicSharedMemorySize,
                         GEMM_SMEM);

    // weight prep (tf32 rna) + input transpose
    cvt_tf32<<<(CD * KK / 4 + 255) / 256, 256>>>(Wq,    (float*)p_wq,  CD * KK / 4);
    cvt_tf32<<<(2 * CD * KK / 4 + 255) / 256, 256>>>(Wkv, (float*)p_wkv, 2 * CD * KK / 4);
    cvt_tf32<<<(CD * KK / 4 + 255) / 256, 256>>>(Wproj, (float*)p_wp,  CD * KK / 4);
    transpose_in<<<dim3(BD, CD / 32), 256>>>(x);

    // q -> qkv[:, 0:1024] ; kv -> qkv[:, 1024:3072]   (x = n-tiles, y = m-tiles)
    gemm_tf32<<<dim3(CD / BN, MM / BM), 256, GEMM_SMEM>>>(
        (const float*)p_xt, (const float*)p_wq, bq, (float*)p_qkv, 3 * CD, 0);
    gemm_tf32<<<dim3(2 * CD / BN, MM / BM), 256, GEMM_SMEM>>>(
        (const float*)p_xt, (const float*)p_wkv, bkv, (float*)p_qkv, 3 * CD, CD);

    attn_kernel<<<BD * HH, 256, ATTN_SMEM_BYTES>>>(rpb, wmix);

    gemm_tf32<<<dim3(CD / BN, MM / BM), 256, GEMM_SMEM>>>(
        (const float*)p_o1, (const float*)p_wp, bproj, (float*)p_o2, CD, 0);

    transpose_out<<<dim3(BD, CD / 32), 256>>>(y);
}

// round 8
// speedup vs baseline: 1.7152x; 1.7152x over previous
#include <cuda_runtime.h>
#include <cuda_fp16.h>
#include <math.h>
#include <cstdint>

// ---------------------------------------------------------------------------
//   x: (B=512, C=1024, 7, 7) -> N = 49 tokens/window, M = B*N = 25088
//   Q = (xt @ Wq^T + bq) * D^-0.5 ; KV = xt @ Wkv^T + bkv
//   attn = mix(softmax, relu^2)(q k^T + rpb) ; o = attn v ; y = o @ Wproj^T + b
// ---------------------------------------------------------------------------
#define BD   512
#define CD   1024
#define NTOK 49
#define HH   8
#define DD   128
#define MM   (BD * NTOK)          // 25088
#define KK   1024

// Device scratch (allocation-free rule: __device__ globals)
__device__ __half g_xt [MM * CD];          // (M, C)   xt, fp16
__device__ float  g_qkv[MM * 3 * CD];      // (M, 3C)  [q | k | v]  fp32
__device__ __half g_o1 [MM * CD];          // (M, C)   attn out, fp16
__device__ float  g_o2 [MM * CD];          // (M, C)   proj out fp32
__device__ __half g_wq [CD * KK];          // fp16 weights
__device__ __half g_wkv[2 * CD * KK];
__device__ __half g_wp [CD * KK];

// ---------------------------------------------------------------------------
// PTX helpers
// ---------------------------------------------------------------------------
__device__ __forceinline__ void cpa16(unsigned dst, const void* src) {
    asm volatile("cp.async.cg.shared.global [%0], [%1], 16;\n" :: "r"(dst), "l"(src));
}
__device__ __forceinline__ void cpa_commit() {
    asm volatile("cp.async.commit_group;\n");
}
__device__ __forceinline__ void cpa_wait1() {
    asm volatile("cp.async.wait_group 1;\n");
}
#define LDSM_X4(r0, r1, r2, r3, addr) \
    asm volatile("ldmatrix.sync.aligned.m8n8.x4.shared.b16 {%0,%1,%2,%3}, [%4];" \
                 : "=r"(r0), "=r"(r1), "=r"(r2), "=r"(r3) : "r"(addr))

__device__ __forceinline__ void mma16(float* c, const unsigned* a, const unsigned* b) {
    asm volatile(
        "mma.sync.aligned.m16n8k16.row.col.f32.f16.f16.f32 "
        "{%0,%1,%2,%3}, {%4,%5,%6,%7}, {%8,%9}, {%0,%1,%2,%3};"
        : "+f"(c[0]), "+f"(c[1]), "+f"(c[2]), "+f"(c[3])
        : "r"(a[0]), "r"(a[1]), "r"(a[2]), "r"(a[3]), "r"(b[0]), "r"(b[1]));
}

// ---------------------------------------------------------------------------
// Kernel 0: elementwise f32 -> f16(rn) copy (weights prep).  n2 = count/2
// ---------------------------------------------------------------------------
__global__ __launch_bounds__(256) void cvt_f16(const float* __restrict__ src,
                                               __half* __restrict__ dst, int n2) {
    int i = blockIdx.x * 256 + threadIdx.x;
    if (i < n2) {
        float2 v = ((const float2*)src)[i];
        ((__half2*)dst)[i] = __floats2half2_rn(v.x, v.y);
    }
}

// ---------------------------------------------------------------------------
// Kernel 1: x (B, C, N) -> xt (M, C), fp16
// ---------------------------------------------------------------------------
__global__ __launch_bounds__(256) void transpose_in(const float* __restrict__ x) {
    __shared__ float t[32][51];
    int b  = blockIdx.x;
    int c0 = blockIdx.y * 32;
    const float* xp = x + (size_t)b * CD * NTOK + (size_t)c0 * NTOK;
    for (int idx = threadIdx.x; idx < 32 * NTOK; idx += 256) {
        int c = idx / NTOK, n = idx - c * NTOK;
        t[c][n] = xp[c * NTOK + n];
    }
    __syncthreads();
    for (int idx = threadIdx.x; idx < 32 * NTOK; idx += 256) {
        int n = idx >> 5, c = idx & 31;
        g_xt[(size_t)(b * NTOK + n) * CD + c0 + c] = __float2half_rn(t[c][n]);
    }
}

// ---------------------------------------------------------------------------
// Kernel 2: fp16 GEMM  C[m, colOff+n] = A[m,:] . W[n,:] + bias[n]   (fp32 acc)
//   A (M,K) fp16 row-major, W (N,K) fp16 row-major.
//   Tile 128x128x64, 3-stage cp.async, 8 warps (2x4), warp tile 64x32,
//   ldmatrix.x4 fragment loads, mma m16n8k16.
//   SMEM rows: 64 halves = 128B = 8 x 16B granules, XOR-swizzled g^(row&7).
// ---------------------------------------------------------------------------
#define BK 64
#define NKT (KK / BK)                // 16
#define TILE_B 16384                 // 128 rows * 128 B
#define STAGE_B (2 * TILE_B)         // A + B
#define GEMM_SMEM (3 * STAGE_B)      // 98304

__global__ __launch_bounds__(256) void gemm_f16(
    const __half* __restrict__ A, const __half* __restrict__ W,
    const float* __restrict__ bias, float* __restrict__ Co,
    int ldc, int colOff)
{
    extern __shared__ __align__(128) unsigned char gsm[];
    const uint32_t smb = (uint32_t)__cvta_generic_to_shared(gsm);

    const int tid  = threadIdx.x;
    const int m0   = blockIdx.y * 128;
    const int n0   = blockIdx.x * 128;
    const int warp = tid >> 5, lane = tid & 31;
    const int wm = warp >> 2, wn = warp & 3;          // 2 x 4

    const __half* Ab = A + (size_t)m0 * KK;
    const __half* Wb = W + (size_t)n0 * KK;

    // per-thread ldmatrix row/granule invariants
    const int l7 = lane & 7;
    int rowA[4], rowB[2];
#pragma unroll
    for (int mi = 0; mi < 4; mi++)
        rowA[mi] = wm * 64 + mi * 16 + l7 + ((lane >> 3) & 1) * 8;
#pragma unroll
    for (int p = 0; p < 2; p++)
        rowB[p] = wn * 32 + p * 16 + l7 + (lane >> 4) * 8;
    const int gaof = lane >> 4;          // A granule sub-offset
    const int gbof = (lane >> 3) & 1;    // B granule sub-offset

    float acc[4][4][4];
#pragma unroll
    for (int mi = 0; mi < 4; mi++)
#pragma unroll
        for (int ni = 0; ni < 4; ni++)
#pragma unroll
            for (int q = 0; q < 4; q++) acc[mi][ni][q] = 0.f;

    // stage fill: 1024 granules A + 1024 granules B, 256 threads x 4
    auto fill = [&](int buf, int kt) {
        uint32_t baseA = smb + buf * STAGE_B;
        uint32_t baseB = baseA + TILE_B;
        int kof = kt * BK;
#pragma unroll
        for (int i = 0; i < 4; i++) {
            int u = i * 256 + tid;
            int row = u >> 3, g = u & 7;
            uint32_t sw = ((uint32_t)(g ^ (row & 7))) << 4;
            cpa16(baseA + row * 128 + sw, Ab + (size_t)row * KK + kof + g * 8);
            cpa16(baseB + row * 128 + sw, Wb + (size_t)row * KK + kof + g * 8);
        }
    };

    fill(0, 0); cpa_commit();
    fill(1, 1); cpa_commit();

    for (int kt = 0; kt < NKT; kt++) {
        int buf = kt % 3;
        cpa_wait1();
        __syncthreads();

        if (kt + 2 < NKT) fill((kt + 2) % 3, kt + 2);
        cpa_commit();

        uint32_t sA = smb + buf * STAGE_B;
        uint32_t sB = sA + TILE_B;

#pragma unroll
        for (int k16 = 0; k16 < 4; k16++) {
            unsigned af[4][4], bf[4][2];
            uint32_t sga = ((uint32_t)((k16 * 2 + gaof) ^ l7)) << 4;
            uint32_t sgb = ((uint32_t)((k16 * 2 + gbof) ^ l7)) << 4;
#pragma unroll
            for (int mi = 0; mi < 4; mi++)
                LDSM_X4(af[mi][0], af[mi][1], af[mi][2], af[mi][3],
                        sA + rowA[mi] * 128 + sga);
#pragma unroll
            for (int p = 0; p < 2; p++)
                LDSM_X4(bf[p * 2][0], bf[p * 2][1], bf[p * 2 + 1][0], bf[p * 2 + 1][1],
                        sB + rowB[p] * 128 + sgb);
#pragma unroll
            for (int mi = 0; mi < 4; mi++)
#pragma unroll
                for (int ni = 0; ni < 4; ni++)
                    mma16(acc[mi][ni], af[mi], bf[ni]);
        }
    }

    // epilogue: + bias, fp32 out
    const int g4 = lane >> 2, t4 = lane & 3;
#pragma unroll
    for (int mi = 0; mi < 4; mi++) {
#pragma unroll
        for (int ni = 0; ni < 4; ni++) {
            int row = m0 + wm * 64 + mi * 16 + g4;
            int col = n0 + wn * 32 + ni * 8 + t4 * 2;
            float b0 = bias[col], b1 = bias[col + 1];
            float2 v0 = { acc[mi][ni][0] + b0, acc[mi][ni][1] + b1 };
            float2 v1 = { acc[mi][ni][2] + b0, acc[mi][ni][3] + b1 };
            *(float2*)&Co[(size_t)row       * ldc + colOff + col] = v0;
            *(float2*)&Co[(size_t)(row + 8) * ldc + colOff + col] = v1;
        }
    }
}

// ---------------------------------------------------------------------------
// Kernel 3: windowed attention per (b, h). 256 threads, 4096 blocks.
// ---------------------------------------------------------------------------
#define QKV_PITCH 132
#define ATTN_SMEM_FLOATS (3 * NTOK * QKV_PITCH + NTOK * NTOK + 169)
#define ATTN_SMEM_BYTES  (ATTN_SMEM_FLOATS * 4)

__global__ __launch_bounds__(256) void attn_kernel(const float* __restrict__ rpb_table,
                                                   const float* __restrict__ w_mix)
{
    extern __shared__ float sm[];
    float* qs = sm;
    float* ks = qs + NTOK * QKV_PITCH;
    float* vs = ks + NTOK * QKV_PITCH;
    float* ss = vs + NTOK * QKV_PITCH;
    float* rp = ss + NTOK * NTOK;

    int bh = blockIdx.x;
    int b = bh >> 3, h = bh & 7;
    int tid = threadIdx.x;

    float wa = w_mix[0], wb = w_mix[1];
    float wmx = fmaxf(wa, wb);
    float ea = __expf(wa - wmx), eb = __expf(wb - wmx);
    float wden = 1.f / (ea + eb);
    float w0 = ea * wden, w1 = eb * wden;

    const float scale = 0.08838834764831845f;      // 128^-0.5 (applied to q)

    size_t base = (size_t)(b * NTOK) * (3 * CD) + h * DD;
    for (int idx = tid; idx < NTOK * DD; idx += 256) {
        int i = idx >> 7, d = idx & 127;
        size_t r = base + (size_t)i * (3 * CD) + d;
        qs[i * QKV_PITCH + d] = g_qkv[r] * scale;
        ks[i * QKV_PITCH + d] = g_qkv[r + CD];
        vs[i * QKV_PITCH + d] = g_qkv[r + 2 * CD];
    }
    for (int idx = tid; idx < 169; idx += 256) rp[idx] = rpb_table[idx * HH + h];
    __syncthreads();

    if (tid < 169) {
        int ti = tid / 13, tj = tid % 13;
        int ib = ti * 4, jb = tj * 4;
        int ri0 = (ib    < 49) ? ib     : 48;
        int ri1 = (ib + 1 < 49) ? ib + 1 : 48;
        int ri2 = (ib + 2 < 49) ? ib + 2 : 48;
        int ri3 = (ib + 3 < 49) ? ib + 3 : 48;
        int rj0 = (jb    < 49) ? jb     : 48;
        int rj1 = (jb + 1 < 49) ? jb + 1 : 48;
        int rj2 = (jb + 2 < 49) ? jb + 2 : 48;
        int rj3 = (jb + 3 < 49) ? jb + 3 : 48;
        const float4* q0 = (const float4*)(qs + ri0 * QKV_PITCH);
        const float4* q1 = (const float4*)(qs + ri1 * QKV_PITCH);
        const float4* q2 = (const float4*)(qs + ri2 * QKV_PITCH);
        const float4* q3 = (const float4*)(qs + ri3 * QKV_PITCH);
        const float4* k0 = (const float4*)(ks + rj0 * QKV_PITCH);
        const float4* k1 = (const float4*)(ks + rj1 * QKV_PITCH);
        const float4* k2 = (const float4*)(ks + rj2 * QKV_PITCH);
        const float4* k3 = (const float4*)(ks + rj3 * QKV_PITCH);

        float acc[4][4];
#pragma unroll
        for (int a = 0; a < 4; a++)
#pragma unroll
            for (int c = 0; c < 4; c++) acc[a][c] = 0.f;

#pragma unroll 4
        for (int t = 0; t < 32; t++) {
            float4 qr[4] = { q0[t], q1[t], q2[t], q3[t] };
            float4 kr[4] = { k0[t], k1[t], k2[t], k3[t] };
#pragma unroll
            for (int a = 0; a < 4; a++)
#pragma unroll
                for (int c = 0; c < 4; c++)
                    acc[a][c] += qr[a].x * kr[c].x + qr[a].y * kr[c].y
                               + qr[a].z * kr[c].z + qr[a].w * kr[c].w;
        }
#pragma unroll
        for (int a = 0; a < 4; a++) {
            int i = ib + a;
            if (i < 49) {
                int ri = i / 7, ci = i - 7 * ri;
#pragma unroll
                for (int c = 0; c < 4; c++) {
                    int j = jb + c;
                    if (j < 49) {
                        int rj = j / 7, cj = j - 7 * rj;
                        ss[i * 49 + j] = acc[a][c]
                                       + rp[(ri - rj + 6) * 13 + (ci - cj + 6)];
                    }
                }
            }
        }
    }
    __syncthreads();

    int warp = tid >> 5, lane = tid & 31;
    for (int r = warp; r < NTOK; r += 8) {
        float x0 = ss[r * NTOK + lane];
        bool v1 = (lane + 32) < NTOK;
        float x1 = v1 ? ss[r * NTOK + lane + 32] : -1e30f;
        float m = fmaxf(x0, x1);
#pragma unroll
        for (int o = 16; o > 0; o >>= 1) m = fmaxf(m, __shfl_xor_sync(0xffffffffu, m, o));
        float p0 = __expf(x0 - m);
        float p1 = v1 ? __expf(x1 - m) : 0.f;
        float s = p0 + p1;
#pragma unroll
        for (int o = 16; o > 0; o >>= 1) s += __shfl_xor_sync(0xffffffffu, s, o);
        float inv = 1.f / s;
        float r0 = fmaxf(x0, 0.f), r1 = fmaxf(x1, 0.f);
        ss[r * NTOK + lane] = w0 * p0 * inv + w1 * r0 * r0;
        if (v1) ss[r * NTOK + lane + 32] = w0 * p1 * inv + w1 * r1 * r1;
    }
    __syncthreads();

    {
        int d = tid & 127, half = tid >> 7;
        size_t obase = (size_t)(b * NTOK) * CD + h * DD + d;
        for (int c = half; c < 7; c += 2) {
            float acc[7] = {0.f, 0.f, 0.f, 0.f, 0.f, 0.f, 0.f};
            const float* sbase = ss + (c * 7) * 49;
#pragma unroll 7
            for (int j = 0; j < 49; j++) {
                float vj = vs[j * QKV_PITCH + d];
#pragma unroll
                for (int ii = 0; ii < 7; ii++)
                    acc[ii] += sbase[ii * 49 + j] * vj;
            }
#pragma unroll
            for (int ii = 0; ii < 7; ii++)
                g_o1[obase + (size_t)(c * 7 + ii) * CD] = __float2half_rn(acc[ii]);
        }
    }
}

// ---------------------------------------------------------------------------
// Kernel 4: o2 (M, C) -> y (B, C, N)
// ---------------------------------------------------------------------------
__global__ __launch_bounds__(256) void transpose_out(float* __restrict__ y) {
    __shared__ float t[NTOK][33];
    int b  = blockIdx.x;
    int c0 = blockIdx.y * 32;
    for (int idx = threadIdx.x; idx < NTOK * 32; idx += 256) {
        int n = idx >> 5, c = idx & 31;
        t[n][c] = g_o2[(size_t)(b * NTOK + n) * CD + c0 + c];
    }
    __syncthreads();
    float* yp = y + (size_t)b * CD * NTOK + (size_t)c0 * NTOK;
    for (int idx = threadIdx.x; idx < 32 * NTOK; idx += 256) {
        int c = idx / NTOK, n = idx - c * NTOK;
        yp[c * NTOK + n] = t[n][c];
    }
}

// ---------------------------------------------------------------------------
// Launch
// ---------------------------------------------------------------------------
extern "C" void kernel_launch(void* const* d_in, const int* in_sizes, int n_in,
                              void* d_out, int out_size)
{
    const float* x     = (const float*)d_in[0];
    const float* Wq    = (const float*)d_in[1];
    const float* bq    = (const float*)d_in[2];
    const float* Wkv   = (const float*)d_in[3];
    const float* bkv   = (const float*)d_in[4];
    const float* rpb   = (const float*)d_in[5];
    const float* wmix  = (const float*)d_in[6];
    const float* Wproj = (const float*)d_in[7];
    const float* bproj = (const float*)d_in[8];
    float* y = (float*)d_out;

    void *p_xt, *p_o1, *p_o2, *p_wq, *p_wkv, *p_wp;
    cudaGetSymbolAddress(&p_xt,  g_xt);
    cudaGetSymbolAddress(&p_o1,  g_o1);
    cudaGetSymbolAddress(&p_o2,  g_o2);
    cudaGetSymbolAddress(&p_wq,  g_wq);
    cudaGetSymbolAddress(&p_wkv, g_wkv);
    cudaGetSymbolAddress(&p_wp,  g_wp);
    void* p_qkv; cudaGetSymbolAddress(&p_qkv, g_qkv);

    cudaFuncSetAttribute(attn_kernel, cudaFuncAttributeMaxDynamicSharedMemorySize,
                         ATTN_SMEM_BYTES);
    cudaFuncSetAttribute(gemm_f16, cudaFuncAttributeMaxDynamicSharedMemorySize,
                         GEMM_SMEM);

    // weight prep (fp16 rn) + input transpose
    cvt_f16<<<(CD * KK / 2 + 255) / 256, 256>>>(Wq,    (__half*)p_wq,  CD * KK / 2);
    cvt_f16<<<(2 * CD * KK / 2 + 255) / 256, 256>>>(Wkv, (__half*)p_wkv, 2 * CD * KK / 2);
    cvt_f16<<<(CD * KK / 2 + 255) / 256, 256>>>(Wproj, (__half*)p_wp,  CD * KK / 2);
    transpose_in<<<dim3(BD, CD / 32), 256>>>(x);

    // q -> qkv[:, 0:1024] ; kv -> qkv[:, 1024:3072]   (x = n-tiles, y = m-tiles)
    gemm_f16<<<dim3(CD / 128, MM / 128), 256, GEMM_SMEM>>>(
        (const __half*)p_xt, (const __half*)p_wq, bq, (float*)p_qkv, 3 * CD, 0);
    gemm_f16<<<dim3(2 * CD / 128, MM / 128), 256, GEMM_SMEM>>>(
        (const __half*)p_xt, (const __half*)p_wkv, bkv, (float*)p_qkv, 3 * CD, CD);

    attn_kernel<<<BD * HH, 256, ATTN_SMEM_BYTES>>>(rpb, wmix);

    gemm_f16<<<dim3(CD / 128, MM / 128), 256, GEMM_SMEM>>>(
        (const __half*)p_o1, (const __half*)p_wp, bproj, (float*)p_o2, CD, 0);

    transpose_out<<<dim3(BD, CD / 32), 256>>>(y);
}

// round 9
// speedup vs baseline: 2.1589x; 1.2587x over previous
#include <cuda_runtime.h>
#include <cuda_fp16.h>
#include <math.h>
#include <cstdint>

// ---------------------------------------------------------------------------
//   x: (B=512, C=1024, 7, 7) -> N = 49 tokens/window, M = B*N = 25088
//   Q = (xt @ Wq^T + bq) * D^-0.5 ; KV = xt @ Wkv^T + bkv
//   attn = mix(softmax, relu^2)(q k^T + rpb) ; o = attn v ; y = o @ Wproj^T + b
// ---------------------------------------------------------------------------
#define BD   512
#define CD   1024
#define NTOK 49
#define HH   8
#define DD   128
#define MM   (BD * NTOK)          // 25088
#define KK   1024

// Device scratch (allocation-free rule: __device__ globals)
__device__ __half g_xt  [MM * CD];          // (M, C)   xt, fp16
__device__ float  g_qkv [MM * 3 * CD];      // (M, 3C)  [q | k | v]  fp32
__device__ __half g_o1  [MM * CD];          // (M, C)   attn out, fp16
__device__ float  g_o2  [MM * CD];          // (M, C)   proj out fp32
__device__ __half g_wqkv[3 * CD * KK];      // [Wq ; Wkv] fp16
__device__ float  g_bqkv[3 * CD];           // [bq ; bkv]
__device__ __half g_wp  [CD * KK];          // Wproj fp16

// ---------------------------------------------------------------------------
// PTX helpers
// ---------------------------------------------------------------------------
__device__ __forceinline__ void cpa16(unsigned dst, const void* src) {
    asm volatile("cp.async.cg.shared.global [%0], [%1], 16;\n" :: "r"(dst), "l"(src));
}
__device__ __forceinline__ void cpa_commit() {
    asm volatile("cp.async.commit_group;\n");
}
__device__ __forceinline__ void cpa_wait1() {
    asm volatile("cp.async.wait_group 1;\n");
}
#define LDSM_X4(r0, r1, r2, r3, addr) \
    asm volatile("ldmatrix.sync.aligned.m8n8.x4.shared.b16 {%0,%1,%2,%3}, [%4];" \
                 : "=r"(r0), "=r"(r1), "=r"(r2), "=r"(r3) : "r"(addr))

__device__ __forceinline__ void mma16(float* c, const unsigned* a, const unsigned* b) {
    asm volatile(
        "mma.sync.aligned.m16n8k16.row.col.f32.f16.f16.f32 "
        "{%0,%1,%2,%3}, {%4,%5,%6,%7}, {%8,%9}, {%0,%1,%2,%3};"
        : "+f"(c[0]), "+f"(c[1]), "+f"(c[2]), "+f"(c[3])
        : "r"(a[0]), "r"(a[1]), "r"(a[2]), "r"(a[3]), "r"(b[0]), "r"(b[1]));
}

// ---------------------------------------------------------------------------
// Kernel 0a: f32 -> f16 copy.  n2 = count/2
// ---------------------------------------------------------------------------
__global__ __launch_bounds__(256) void cvt_f16(const float* __restrict__ src,
                                               __half* __restrict__ dst, int n2) {
    int i = blockIdx.x * 256 + threadIdx.x;
    if (i < n2) {
        float2 v = ((const float2*)src)[i];
        ((__half2*)dst)[i] = __floats2half2_rn(v.x, v.y);
    }
}
// Kernel 0b: concat [bq ; bkv] -> g_bqkv
__global__ __launch_bounds__(256) void concat_bias(const float* __restrict__ bq,
                                                   const float* __restrict__ bkv,
                                                   float* __restrict__ dst) {
    int i = blockIdx.x * 256 + threadIdx.x;
    if (i < CD) dst[i] = bq[i];
    else if (i < 3 * CD) dst[i] = bkv[i - CD];
}

// ---------------------------------------------------------------------------
// Kernel 1: x (B, C, N) -> xt (M, C), fp16
// ---------------------------------------------------------------------------
__global__ __launch_bounds__(256) void transpose_in(const float* __restrict__ x) {
    __shared__ float t[32][51];
    int b  = blockIdx.x;
    int c0 = blockIdx.y * 32;
    const float* xp = x + (size_t)b * CD * NTOK + (size_t)c0 * NTOK;
    for (int idx = threadIdx.x; idx < 32 * NTOK; idx += 256) {
        int c = idx / NTOK, n = idx - c * NTOK;
        t[c][n] = xp[c * NTOK + n];
    }
    __syncthreads();
    for (int idx = threadIdx.x; idx < 32 * NTOK; idx += 256) {
        int n = idx >> 5, c = idx & 31;
        g_xt[(size_t)(b * NTOK + n) * CD + c0 + c] = __float2half_rn(t[c][n]);
    }
}

// ---------------------------------------------------------------------------
// Kernel 2: fp16 GEMM  C[m, colOff+n] = A[m,:] . W[n,:] + bias[n]   (fp32 acc)
//   Tile 128x128x64, 3-stage cp.async, 8 warps (2x4), ldmatrix.x4, mma k16.
// ---------------------------------------------------------------------------
#define BK 64
#define NKT (KK / BK)                // 16
#define TILE_B 16384                 // 128 rows * 128 B
#define STAGE_B (2 * TILE_B)
#define GEMM_SMEM (3 * STAGE_B)      // 98304

__global__ __launch_bounds__(256) void gemm_f16(
    const __half* __restrict__ A, const __half* __restrict__ W,
    const float* __restrict__ bias, float* __restrict__ Co,
    int ldc, int colOff)
{
    extern __shared__ __align__(128) unsigned char gsm[];
    const uint32_t smb = (uint32_t)__cvta_generic_to_shared(gsm);

    const int tid  = threadIdx.x;
    const int m0   = blockIdx.y * 128;
    const int n0   = blockIdx.x * 128;
    const int warp = tid >> 5, lane = tid & 31;
    const int wm = warp >> 2, wn = warp & 3;          // 2 x 4

    const __half* Ab = A + (size_t)m0 * KK;
    const __half* Wb = W + (size_t)n0 * KK;

    const int l7 = lane & 7;
    int rowA[4], rowB[2];
#pragma unroll
    for (int mi = 0; mi < 4; mi++)
        rowA[mi] = wm * 64 + mi * 16 + l7 + ((lane >> 3) & 1) * 8;
#pragma unroll
    for (int p = 0; p < 2; p++)
        rowB[p] = wn * 32 + p * 16 + l7 + (lane >> 4) * 8;
    const int gaof = lane >> 4;
    const int gbof = (lane >> 3) & 1;

    float acc[4][4][4];
#pragma unroll
    for (int mi = 0; mi < 4; mi++)
#pragma unroll
        for (int ni = 0; ni < 4; ni++)
#pragma unroll
            for (int q = 0; q < 4; q++) acc[mi][ni][q] = 0.f;

    auto fill = [&](int buf, int kt) {
        uint32_t baseA = smb + buf * STAGE_B;
        uint32_t baseB = baseA + TILE_B;
        int kof = kt * BK;
#pragma unroll
        for (int i = 0; i < 4; i++) {
            int u = i * 256 + tid;
            int row = u >> 3, g = u & 7;
            uint32_t sw = ((uint32_t)(g ^ (row & 7))) << 4;
            cpa16(baseA + row * 128 + sw, Ab + (size_t)row * KK + kof + g * 8);
            cpa16(baseB + row * 128 + sw, Wb + (size_t)row * KK + kof + g * 8);
        }
    };

    fill(0, 0); cpa_commit();
    fill(1, 1); cpa_commit();

    for (int kt = 0; kt < NKT; kt++) {
        int buf = kt % 3;
        cpa_wait1();
        __syncthreads();

        if (kt + 2 < NKT) fill((kt + 2) % 3, kt + 2);
        cpa_commit();

        uint32_t sA = smb + buf * STAGE_B;
        uint32_t sB = sA + TILE_B;

#pragma unroll
        for (int k16 = 0; k16 < 4; k16++) {
            unsigned af[4][4], bf[4][2];
            uint32_t sga = ((uint32_t)((k16 * 2 + gaof) ^ l7)) << 4;
            uint32_t sgb = ((uint32_t)((k16 * 2 + gbof) ^ l7)) << 4;
#pragma unroll
            for (int mi = 0; mi < 4; mi++)
                LDSM_X4(af[mi][0], af[mi][1], af[mi][2], af[mi][3],
                        sA + rowA[mi] * 128 + sga);
#pragma unroll
            for (int p = 0; p < 2; p++)
                LDSM_X4(bf[p * 2][0], bf[p * 2][1], bf[p * 2 + 1][0], bf[p * 2 + 1][1],
                        sB + rowB[p] * 128 + sgb);
#pragma unroll
            for (int mi = 0; mi < 4; mi++)
#pragma unroll
                for (int ni = 0; ni < 4; ni++)
                    mma16(acc[mi][ni], af[mi], bf[ni]);
        }
    }

    const int g4 = lane >> 2, t4 = lane & 3;
#pragma unroll
    for (int mi = 0; mi < 4; mi++) {
#pragma unroll
        for (int ni = 0; ni < 4; ni++) {
            int row = m0 + wm * 64 + mi * 16 + g4;
            int col = n0 + wn * 32 + ni * 8 + t4 * 2;
            float b0 = bias[col], b1 = bias[col + 1];
            float2 v0 = { acc[mi][ni][0] + b0, acc[mi][ni][1] + b1 };
            float2 v1 = { acc[mi][ni][2] + b0, acc[mi][ni][3] + b1 };
            *(float2*)&Co[(size_t)row       * ldc + colOff + col] = v0;
            *(float2*)&Co[(size_t)(row + 8) * ldc + colOff + col] = v1;
        }
    }
}

// ---------------------------------------------------------------------------
// Kernel 3: tensor-core windowed attention per (b, h). 256 threads, 4096 blocks.
//   S = q k^T via mma (64x64x128 padded), softmax/mix fp32 in smem,
//   O = attn v via mma (64x128x64 padded), staged coalesced fp16 store.
//   Pitches (16B granules): q/k 272B/row, vT/attn 144B/row, S 272B/row —
//   granule strides 17/9/17 are odd => conflict-free LDSM.
// ---------------------------------------------------------------------------
#define AP 136            // halves per q/k row (272 B)
#define VP 72             // halves per vT/attn row (144 B)
#define SP 68             // floats per S row (272 B)
#define ATTN_TC_SMEM (2 * 64 * AP * 2 + 128 * VP * 2 + 64 * SP * 4 + 64 * VP * 2 + 704)

__global__ __launch_bounds__(256) void attn_tc(const float* __restrict__ rpb_table,
                                               const float* __restrict__ w_mix)
{
    extern __shared__ __align__(16) unsigned char asmm[];
    __half* qs = (__half*)asmm;                 // 64 x AP   (later: O staging)
    __half* ks = qs + 64 * AP;                  // 64 x AP
    __half* vt = ks + 64 * AP;                  // 128 x VP  (vT: row=d, col=j)
    float*  ss = (float*)(vt + 128 * VP);       // 64 x SP
    __half* at = (__half*)(ss + 64 * SP);       // 64 x VP
    float*  rp = (float*)(at + 64 * VP);        // 169

    const int bh = blockIdx.x;
    const int b = bh >> 3, h = bh & 7;
    const int tid = threadIdx.x;
    const int warp = tid >> 5, lane = tid & 31;

    // mix weights (uniform)
    float wa = w_mix[0], wb = w_mix[1];
    float wmx = fmaxf(wa, wb);
    float ea = __expf(wa - wmx), eb = __expf(wb - wmx);
    float wden = 1.f / (ea + eb);
    float w0 = ea * wden, w1 = eb * wden;

    const float scale = 0.08838834764831845f;   // 128^-0.5 (applied to q)
    size_t base = (size_t)(b * NTOK) * (3 * CD) + h * DD;

    // ---- load q, k (64x128, zero-padded rows), vT (128x64, zero-padded cols)
    for (int idx = tid; idx < 64 * DD; idx += 256) {
        int i = idx >> 7, d = idx & 127;
        float qv = 0.f, kv = 0.f;
        if (i < NTOK) {
            size_t r = base + (size_t)i * (3 * CD) + d;
            qv = g_qkv[r] * scale;
            kv = g_qkv[r + CD];
        }
        qs[i * AP + d] = __float2half_rn(qv);
        ks[i * AP + d] = __float2half_rn(kv);
    }
    for (int idx = tid; idx < 64 * DD; idx += 256) {
        int j = idx >> 7, d = idx & 127;
        float vv = (j < NTOK) ? g_qkv[base + (size_t)j * (3 * CD) + 2 * CD + d] : 0.f;
        vt[d * VP + j] = __float2half_rn(vv);
    }
    for (int idx = tid; idx < 169; idx += 256) rp[idx] = rpb_table[idx * HH + h];
    __syncthreads();

    const uint32_t qb = (uint32_t)__cvta_generic_to_shared(qs);
    const uint32_t kb = (uint32_t)__cvta_generic_to_shared(ks);
    const uint32_t vb = (uint32_t)__cvta_generic_to_shared(vt);
    const uint32_t ab = (uint32_t)__cvta_generic_to_shared(at);

    const int wm = warp >> 1, wn = warp & 1;    // 4 x 2
    const int l7 = lane & 7;
    const int rA  = wm * 16 + l7 + ((lane >> 3) & 1) * 8;
    const int gaof = lane >> 4, gbof = (lane >> 3) & 1;
    const int g4 = lane >> 2, t4 = lane & 3;

    // ---- S = q k^T  (M=64, N=64, K=128); warp tile 16 x 32
    {
        float sc[4][4];
#pragma unroll
        for (int ni = 0; ni < 4; ni++)
#pragma unroll
            for (int q = 0; q < 4; q++) sc[ni][q] = 0.f;

        const int rB0 = wn * 32 + l7 + (lane >> 4) * 8;
        const int rB1 = rB0 + 16;
#pragma unroll
        for (int k16 = 0; k16 < 8; k16++) {
            unsigned af[4], bf[4][2];
            LDSM_X4(af[0], af[1], af[2], af[3],
                    qb + rA * 272 + (k16 * 2 + gaof) * 16);
            LDSM_X4(bf[0][0], bf[0][1], bf[1][0], bf[1][1],
                    kb + rB0 * 272 + (k16 * 2 + gbof) * 16);
            LDSM_X4(bf[2][0], bf[2][1], bf[3][0], bf[3][1],
                    kb + rB1 * 272 + (k16 * 2 + gbof) * 16);
#pragma unroll
            for (int ni = 0; ni < 4; ni++) mma16(sc[ni], af, bf[ni]);
        }
#pragma unroll
        for (int ni = 0; ni < 4; ni++) {
            int row = wm * 16 + g4;
            int col = wn * 32 + ni * 8 + t4 * 2;
            ss[row * SP + col]           = sc[ni][0];
            ss[row * SP + col + 1]       = sc[ni][1];
            ss[(row + 8) * SP + col]     = sc[ni][2];
            ss[(row + 8) * SP + col + 1] = sc[ni][3];
        }
    }
    __syncthreads();

    // ---- softmax + relu^2 mix (one warp per row), write attn fp16 (+pads)
    for (int r = warp; r < NTOK; r += 8) {
        int ri = r / 7, ci = r - 7 * ri;
        int j0 = lane;
        int rj0 = j0 / 7, cj0 = j0 - 7 * rj0;
        float x0 = ss[r * SP + j0] + rp[(ri - rj0 + 6) * 13 + (ci - cj0 + 6)];
        int j1 = lane + 32;
        bool v1 = j1 < NTOK;
        float x1 = -1e30f;
        if (v1) {
            int rj1 = j1 / 7, cj1 = j1 - 7 * rj1;
            x1 = ss[r * SP + j1] + rp[(ri - rj1 + 6) * 13 + (ci - cj1 + 6)];
        }
        float m = fmaxf(x0, x1);
#pragma unroll
        for (int o = 16; o > 0; o >>= 1) m = fmaxf(m, __shfl_xor_sync(0xffffffffu, m, o));
        float p0 = __expf(x0 - m);
        float p1 = v1 ? __expf(x1 - m) : 0.f;
        float s = p0 + p1;
#pragma unroll
        for (int o = 16; o > 0; o >>= 1) s += __shfl_xor_sync(0xffffffffu, s, o);
        float inv = 1.f / s;
        float r0 = fmaxf(x0, 0.f), r1 = fmaxf(x1, 0.f);
        at[r * VP + j0] = __float2half_rn(w0 * p0 * inv + w1 * r0 * r0);
        at[r * VP + j1] = v1 ? __float2half_rn(w0 * p1 * inv + w1 * r1 * r1)
                             : __half(0.f);
    }
    // zero pad rows 49..63 of attn
    for (int idx = tid; idx < (64 - NTOK) * 64; idx += 256) {
        int r = NTOK + idx / 64, c = idx & 63;
        at[r * VP + c] = __half(0.f);
    }
    __syncthreads();

    // ---- O = attn @ v  (M=64, N=128, K=64); warp tile 16 x 64
    float oc[8][4];
#pragma unroll
    for (int ni = 0; ni < 8; ni++)
#pragma unroll
        for (int q = 0; q < 4; q++) oc[ni][q] = 0.f;

#pragma unroll
    for (int k16 = 0; k16 < 4; k16++) {
        unsigned af[4], bf[8][2];
        LDSM_X4(af[0], af[1], af[2], af[3],
                ab + rA * 144 + (k16 * 2 + gaof) * 16);
#pragma unroll
        for (int np = 0; np < 4; np++) {
            int rBv = wn * 64 + np * 16 + l7 + (lane >> 4) * 8;
            LDSM_X4(bf[np * 2][0], bf[np * 2][1], bf[np * 2 + 1][0], bf[np * 2 + 1][1],
                    vb + rBv * 144 + (k16 * 2 + gbof) * 16);
        }
#pragma unroll
        for (int ni = 0; ni < 8; ni++) mma16(oc[ni], af, bf[ni]);
    }
    __syncthreads();            // q buffer free; reuse as O staging

    // stage O (fp16) into qs, then coalesced store rows i<49
#pragma unroll
    for (int ni = 0; ni < 8; ni++) {
        int row = wm * 16 + g4;
        int col = wn * 64 + ni * 8 + t4 * 2;
        qs[row * AP + col]           = __float2half_rn(oc[ni][0]);
        qs[row * AP + col + 1]       = __float2half_rn(oc[ni][1]);
        qs[(row + 8) * AP + col]     = __float2half_rn(oc[ni][2]);
        qs[(row + 8) * AP + col + 1] = __float2half_rn(oc[ni][3]);
    }
    __syncthreads();
    for (int idx = tid; idx < NTOK * 16; idx += 256) {
        int i = idx >> 4, c4 = idx & 15;
        uint4 v = *(uint4*)(qs + i * AP + c4 * 8);
        *(uint4*)(&g_o1[(size_t)(b * NTOK + i) * CD + h * DD + c4 * 8]) = v;
    }
}

// ---------------------------------------------------------------------------
// Kernel 4: o2 (M, C) -> y (B, C, N)
// ---------------------------------------------------------------------------
__global__ __launch_bounds__(256) void transpose_out(float* __restrict__ y) {
    __shared__ float t[NTOK][33];
    int b  = blockIdx.x;
    int c0 = blockIdx.y * 32;
    for (int idx = threadIdx.x; idx < NTOK * 32; idx += 256) {
        int n = idx >> 5, c = idx & 31;
        t[n][c] = g_o2[(size_t)(b * NTOK + n) * CD + c0 + c];
    }
    __syncthreads();
    float* yp = y + (size_t)b * CD * NTOK + (size_t)c0 * NTOK;
    for (int idx = threadIdx.x; idx < 32 * NTOK; idx += 256) {
        int c = idx / NTOK, n = idx - c * NTOK;
        yp[c * NTOK + n] = t[n][c];
    }
}

// ---------------------------------------------------------------------------
// Launch
// ---------------------------------------------------------------------------
extern "C" void kernel_launch(void* const* d_in, const int* in_sizes, int n_in,
                              void* d_out, int out_size)
{
    const float* x     = (const float*)d_in[0];
    const float* Wq    = (const float*)d_in[1];
    const float* bq    = (const float*)d_in[2];
    const float* Wkv   = (const float*)d_in[3];
    const float* bkv   = (const float*)d_in[4];
    const float* rpb   = (const float*)d_in[5];
    const float* wmix  = (const float*)d_in[6];
    const float* Wproj = (const float*)d_in[7];
    const float* bproj = (const float*)d_in[8];
    float* y = (float*)d_out;

    void *p_xt, *p_qkv, *p_o1, *p_o2, *p_wqkv, *p_bqkv, *p_wp;
    cudaGetSymbolAddress(&p_xt,   g_xt);
    cudaGetSymbolAddress(&p_qkv,  g_qkv);
    cudaGetSymbolAddress(&p_o1,   g_o1);
    cudaGetSymbolAddress(&p_o2,   g_o2);
    cudaGetSymbolAddress(&p_wqkv, g_wqkv);
    cudaGetSymbolAddress(&p_bqkv, g_bqkv);
    cudaGetSymbolAddress(&p_wp,   g_wp);

    cudaFuncSetAttribute(attn_tc, cudaFuncAttributeMaxDynamicSharedMemorySize,
                         ATTN_TC_SMEM);
    cudaFuncSetAttribute(gemm_f16, cudaFuncAttributeMaxDynamicSharedMemorySize,
                         GEMM_SMEM);

    // prep: weights fp16 (Wq, Wkv into one buffer), bias concat, x transpose
    cvt_f16<<<(CD * KK / 2 + 255) / 256, 256>>>(Wq, (__half*)p_wqkv, CD * KK / 2);
    cvt_f16<<<(2 * CD * KK / 2 + 255) / 256, 256>>>(
        Wkv, (__half*)p_wqkv + (size_t)CD * KK, 2 * CD * KK / 2);
    cvt_f16<<<(CD * KK / 2 + 255) / 256, 256>>>(Wproj, (__half*)p_wp, CD * KK / 2);
    concat_bias<<<(3 * CD + 255) / 256, 256>>>(bq, bkv, (float*)p_bqkv);
    transpose_in<<<dim3(BD, CD / 32), 256>>>(x);

    // single fused QKV GEMM: N = 3072
    gemm_f16<<<dim3(3 * CD / 128, MM / 128), 256, GEMM_SMEM>>>(
        (const __half*)p_xt, (const __half*)p_wqkv, (const float*)p_bqkv,
        (float*)p_qkv, 3 * CD, 0);

    attn_tc<<<BD * HH, 256, ATTN_TC_SMEM>>>(rpb, wmix);

    gemm_f16<<<dim3(CD / 128, MM / 128), 256, GEMM_SMEM>>>(
        (const __half*)p_o1, (const __half*)p_wp, bproj, (float*)p_o2, CD, 0);

    transpose_out<<<dim3(BD, CD / 32), 256>>>(y);
}

// round 10
// speedup vs baseline: 2.3293x; 1.0789x over previous
#include <cuda_runtime.h>
#include <cuda_fp16.h>
#include <math.h>
#include <cstdint>

// ---------------------------------------------------------------------------
//   x: (B=512, C=1024, 7, 7) -> N = 49 tokens/window, M = B*N = 25088
//   Q = (xt @ Wq^T + bq) * D^-0.5 ; KV = xt @ Wkv^T + bkv
//   attn = mix(softmax, relu^2)(q k^T + rpb) ; o = attn v ; y = o @ Wproj^T + b
// ---------------------------------------------------------------------------
#define BD   512
#define CD   1024
#define NTOK 49
#define HH   8
#define DD   128
#define MM   (BD * NTOK)          // 25088
#define KK   1024

// Device scratch (allocation-free rule: __device__ globals)
__device__ __half g_xt  [MM * CD];          // (M, C)   xt, fp16
__device__ float  g_qkv [MM * 3 * CD];      // (M, 3C)  [q | k | v]  fp32
__device__ __half g_o1  [MM * CD];          // (M, C)   attn out, fp16
__device__ __half g_wqkv[3 * CD * KK];      // [Wq ; Wkv] fp16
__device__ float  g_bqkv[3 * CD];           // [bq ; bkv]
__device__ __half g_wp  [CD * KK];          // Wproj fp16

// ---------------------------------------------------------------------------
// PTX helpers
// ---------------------------------------------------------------------------
__device__ __forceinline__ void cpa16(unsigned dst, const void* src) {
    asm volatile("cp.async.cg.shared.global [%0], [%1], 16;\n" :: "r"(dst), "l"(src));
}
__device__ __forceinline__ void cpa_commit() {
    asm volatile("cp.async.commit_group;\n");
}
__device__ __forceinline__ void cpa_wait1() {
    asm volatile("cp.async.wait_group 1;\n");
}
#define LDSM_X4(r0, r1, r2, r3, addr) \
    asm volatile("ldmatrix.sync.aligned.m8n8.x4.shared.b16 {%0,%1,%2,%3}, [%4];" \
                 : "=r"(r0), "=r"(r1), "=r"(r2), "=r"(r3) : "r"(addr))

__device__ __forceinline__ void mma16(float* c, const unsigned* a, const unsigned* b) {
    asm volatile(
        "mma.sync.aligned.m16n8k16.row.col.f32.f16.f16.f32 "
        "{%0,%1,%2,%3}, {%4,%5,%6,%7}, {%8,%9}, {%0,%1,%2,%3};"
        : "+f"(c[0]), "+f"(c[1]), "+f"(c[2]), "+f"(c[3])
        : "r"(a[0]), "r"(a[1]), "r"(a[2]), "r"(a[3]), "r"(b[0]), "r"(b[1]));
}

// ---------------------------------------------------------------------------
// Kernel 0: one-shot prep — all weights f32->f16 + bias concat
//   ranges (in half2 units): [0, NQ) Wq -> wqkv, [NQ, NQ+NKV) Wkv -> wqkv+,
//   [NQ+NKV, NQ+NKV+NP) Wproj -> wp ; tail 3*CD threads do bias concat
// ---------------------------------------------------------------------------
#define NQ  (CD * KK / 2)
#define NKV (2 * CD * KK / 2)
#define NP  (CD * KK / 2)
#define PREP_TOTAL (NQ + NKV + NP + 3 * CD)

__global__ __launch_bounds__(256) void prep_kernel(
    const float* __restrict__ Wq, const float* __restrict__ Wkv,
    const float* __restrict__ Wproj,
    const float* __restrict__ bq, const float* __restrict__ bkv)
{
    int i = blockIdx.x * 256 + threadIdx.x;
    if (i < NQ) {
        float2 v = ((const float2*)Wq)[i];
        ((__half2*)g_wqkv)[i] = __floats2half2_rn(v.x, v.y);
    } else if (i < NQ + NKV) {
        int j = i - NQ;
        float2 v = ((const float2*)Wkv)[j];
        ((__half2*)g_wqkv)[NQ + j] = __floats2half2_rn(v.x, v.y);
    } else if (i < NQ + NKV + NP) {
        int j = i - NQ - NKV;
        float2 v = ((const float2*)Wproj)[j];
        ((__half2*)g_wp)[j] = __floats2half2_rn(v.x, v.y);
    } else if (i < PREP_TOTAL) {
        int j = i - NQ - NKV - NP;
        g_bqkv[j] = (j < CD) ? bq[j] : bkv[j - CD];
    }
}

// ---------------------------------------------------------------------------
// Kernel 1: x (B, C, N) -> xt (M, C), fp16, fully-coalesced half2 stores
//   64 channels per block, smem [49][65] (n-major, odd pitch)
// ---------------------------------------------------------------------------
__global__ __launch_bounds__(256) void transpose_in(const float* __restrict__ x) {
    __shared__ float t[NTOK][65];
    int b  = blockIdx.x;
    int c0 = blockIdx.y * 64;
    const float* xp = x + (size_t)b * CD * NTOK + (size_t)c0 * NTOK;
    for (int idx = threadIdx.x; idx < 64 * NTOK; idx += 256) {
        int c = idx / NTOK, n = idx - c * NTOK;
        t[n][c] = xp[c * NTOK + n];
    }
    __syncthreads();
    for (int idx = threadIdx.x; idx < NTOK * 32; idx += 256) {
        int n = idx >> 5, p = idx & 31;
        __half2 h = __floats2half2_rn(t[n][2 * p], t[n][2 * p + 1]);
        *(__half2*)&g_xt[(size_t)(b * NTOK + n) * CD + c0 + 2 * p] = h;
    }
}

// ---------------------------------------------------------------------------
// Kernel 2: fp16 GEMM  (fp32 acc), tile 128x128x64, 3-stage cp.async,
//   8 warps (2x4), ldmatrix.x4, mma m16n8k16.
//   mode 0: Co[row, colOff+col] = acc + bias  (fp32, ldc)
//   mode 1: y[b, col, n] = acc + bias  (fused output transpose; row = b*49+n)
// ---------------------------------------------------------------------------
#define BK 64
#define NKT (KK / BK)                // 16
#define TILE_B 16384                 // 128 rows * 128 B
#define STAGE_B (2 * TILE_B)
#define GEMM_SMEM (3 * STAGE_B)      // 98304  (>= 128*129*4 = 66048 epi staging)

__global__ __launch_bounds__(256) void gemm_f16(
    const __half* __restrict__ A, const __half* __restrict__ W,
    const float* __restrict__ bias, float* __restrict__ Co,
    int ldc, int colOff, int mode)
{
    extern __shared__ __align__(128) unsigned char gsm[];
    const uint32_t smb = (uint32_t)__cvta_generic_to_shared(gsm);

    const int tid  = threadIdx.x;
    const int m0   = blockIdx.y * 128;
    const int n0   = blockIdx.x * 128;
    const int warp = tid >> 5, lane = tid & 31;
    const int wm = warp >> 2, wn = warp & 3;          // 2 x 4

    const __half* Ab = A + (size_t)m0 * KK;
    const __half* Wb = W + (size_t)n0 * KK;

    const int l7 = lane & 7;
    int rowA[4], rowB[2];
#pragma unroll
    for (int mi = 0; mi < 4; mi++)
        rowA[mi] = wm * 64 + mi * 16 + l7 + ((lane >> 3) & 1) * 8;
#pragma unroll
    for (int p = 0; p < 2; p++)
        rowB[p] = wn * 32 + p * 16 + l7 + (lane >> 4) * 8;
    const int gaof = lane >> 4;
    const int gbof = (lane >> 3) & 1;

    float acc[4][4][4];
#pragma unroll
    for (int mi = 0; mi < 4; mi++)
#pragma unroll
        for (int ni = 0; ni < 4; ni++)
#pragma unroll
            for (int q = 0; q < 4; q++) acc[mi][ni][q] = 0.f;

    auto fill = [&](int buf, int kt) {
        uint32_t baseA = smb + buf * STAGE_B;
        uint32_t baseB = baseA + TILE_B;
        int kof = kt * BK;
#pragma unroll
        for (int i = 0; i < 4; i++) {
            int u = i * 256 + tid;
            int row = u >> 3, g = u & 7;
            uint32_t sw = ((uint32_t)(g ^ (row & 7))) << 4;
            cpa16(baseA + row * 128 + sw, Ab + (size_t)row * KK + kof + g * 8);
            cpa16(baseB + row * 128 + sw, Wb + (size_t)row * KK + kof + g * 8);
        }
    };

    fill(0, 0); cpa_commit();
    fill(1, 1); cpa_commit();

    for (int kt = 0; kt < NKT; kt++) {
        int buf = kt % 3;
        cpa_wait1();
        __syncthreads();

        if (kt + 2 < NKT) fill((kt + 2) % 3, kt + 2);
        cpa_commit();

        uint32_t sA = smb + buf * STAGE_B;
        uint32_t sB = sA + TILE_B;

#pragma unroll
        for (int k16 = 0; k16 < 4; k16++) {
            unsigned af[4][4], bf[4][2];
            uint32_t sga = ((uint32_t)((k16 * 2 + gaof) ^ l7)) << 4;
            uint32_t sgb = ((uint32_t)((k16 * 2 + gbof) ^ l7)) << 4;
#pragma unroll
            for (int mi = 0; mi < 4; mi++)
                LDSM_X4(af[mi][0], af[mi][1], af[mi][2], af[mi][3],
                        sA + rowA[mi] * 128 + sga);
#pragma unroll
            for (int p = 0; p < 2; p++)
                LDSM_X4(bf[p * 2][0], bf[p * 2][1], bf[p * 2 + 1][0], bf[p * 2 + 1][1],
                        sB + rowB[p] * 128 + sgb);
#pragma unroll
            for (int mi = 0; mi < 4; mi++)
#pragma unroll
                for (int ni = 0; ni < 4; ni++)
                    mma16(acc[mi][ni], af[mi], bf[ni]);
        }
    }

    const int g4 = lane >> 2, t4 = lane & 3;
    if (mode == 0) {
#pragma unroll
        for (int mi = 0; mi < 4; mi++) {
#pragma unroll
            for (int ni = 0; ni < 4; ni++) {
                int row = m0 + wm * 64 + mi * 16 + g4;
                int col = n0 + wn * 32 + ni * 8 + t4 * 2;
                float b0 = bias[col], b1 = bias[col + 1];
                float2 v0 = { acc[mi][ni][0] + b0, acc[mi][ni][1] + b1 };
                float2 v1 = { acc[mi][ni][2] + b0, acc[mi][ni][3] + b1 };
                *(float2*)&Co[(size_t)row       * ldc + colOff + col] = v0;
                *(float2*)&Co[(size_t)(row + 8) * ldc + colOff + col] = v1;
            }
        }
    } else {
        // fused output transpose: stage (+bias) into smem [128][129], then
        // write y[b, col, n] with r-contiguous (n-contiguous) runs
        __syncthreads();                    // pipeline buffers now free
        float* st = (float*)gsm;
#pragma unroll
        for (int mi = 0; mi < 4; mi++) {
#pragma unroll
            for (int ni = 0; ni < 4; ni++) {
                int row = wm * 64 + mi * 16 + g4;
                int col = wn * 32 + ni * 8 + t4 * 2;
                float b0 = bias[n0 + col], b1 = bias[n0 + col + 1];
                st[row * 129 + col]           = acc[mi][ni][0] + b0;
                st[row * 129 + col + 1]       = acc[mi][ni][1] + b1;
                st[(row + 8) * 129 + col]     = acc[mi][ni][2] + b0;
                st[(row + 8) * 129 + col + 1] = acc[mi][ni][3] + b1;
            }
        }
        __syncthreads();
        for (int idx = tid; idx < 128 * 128; idx += 256) {
            int c = idx >> 7, r = idx & 127;
            int grow = m0 + r;
            int b = grow / NTOK, n = grow - b * NTOK;
            Co[(size_t)b * CD * NTOK + (size_t)(n0 + c) * NTOK + n] = st[r * 129 + c];
        }
    }
}

// ---------------------------------------------------------------------------
// Kernel 3: tensor-core windowed attention per (b, h). 256 threads, 4096 blocks.
// ---------------------------------------------------------------------------
#define AP 136            // halves per q/k row (272 B)
#define VP 72             // halves per vT/attn row (144 B)
#define SP 68             // floats per S row (272 B)
#define ATTN_TC_SMEM (2 * 64 * AP * 2 + 128 * VP * 2 + 64 * SP * 4 + 64 * VP * 2 + 704)

__global__ __launch_bounds__(256) void attn_tc(const float* __restrict__ rpb_table,
                                               const float* __restrict__ w_mix)
{
    extern __shared__ __align__(16) unsigned char asmm[];
    __half* qs = (__half*)asmm;                 // 64 x AP   (later: O staging)
    __half* ks = qs + 64 * AP;                  // 64 x AP
    __half* vt = ks + 64 * AP;                  // 128 x VP  (vT: row=d, col=j)
    float*  ss = (float*)(vt + 128 * VP);       // 64 x SP
    __half* at = (__half*)(ss + 64 * SP);       // 64 x VP
    float*  rp = (float*)(at + 64 * VP);        // 169

    const int bh = blockIdx.x;
    const int b = bh >> 3, h = bh & 7;
    const int tid = threadIdx.x;
    const int warp = tid >> 5, lane = tid & 31;

    float wa = w_mix[0], wb = w_mix[1];
    float wmx = fmaxf(wa, wb);
    float ea = __expf(wa - wmx), eb = __expf(wb - wmx);
    float wden = 1.f / (ea + eb);
    float w0 = ea * wden, w1 = eb * wden;

    const float scale = 0.08838834764831845f;   // 128^-0.5 (applied to q)
    size_t base = (size_t)(b * NTOK) * (3 * CD) + h * DD;

    for (int idx = tid; idx < 64 * DD; idx += 256) {
        int i = idx >> 7, d = idx & 127;
        float qv = 0.f, kv = 0.f;
        if (i < NTOK) {
            size_t r = base + (size_t)i * (3 * CD) + d;
            qv = g_qkv[r] * scale;
            kv = g_qkv[r + CD];
        }
        qs[i * AP + d] = __float2half_rn(qv);
        ks[i * AP + d] = __float2half_rn(kv);
    }
    for (int idx = tid; idx < 64 * DD; idx += 256) {
        int j = idx >> 7, d = idx & 127;
        float vv = (j < NTOK) ? g_qkv[base + (size_t)j * (3 * CD) + 2 * CD + d] : 0.f;
        vt[d * VP + j] = __float2half_rn(vv);
    }
    for (int idx = tid; idx < 169; idx += 256) rp[idx] = rpb_table[idx * HH + h];
    __syncthreads();

    const uint32_t qb = (uint32_t)__cvta_generic_to_shared(qs);
    const uint32_t kb = (uint32_t)__cvta_generic_to_shared(ks);
    const uint32_t vb = (uint32_t)__cvta_generic_to_shared(vt);
    const uint32_t ab = (uint32_t)__cvta_generic_to_shared(at);

    const int wm = warp >> 1, wn = warp & 1;    // 4 x 2
    const int l7 = lane & 7;
    const int rA  = wm * 16 + l7 + ((lane >> 3) & 1) * 8;
    const int gaof = lane >> 4, gbof = (lane >> 3) & 1;
    const int g4 = lane >> 2, t4 = lane & 3;

    // ---- S = q k^T  (M=64, N=64, K=128)
    {
        float sc[4][4];
#pragma unroll
        for (int ni = 0; ni < 4; ni++)
#pragma unroll
            for (int q = 0; q < 4; q++) sc[ni][q] = 0.f;

        const int rB0 = wn * 32 + l7 + (lane >> 4) * 8;
        const int rB1 = rB0 + 16;
#pragma unroll
        for (int k16 = 0; k16 < 8; k16++) {
            unsigned af[4], bf[4][2];
            LDSM_X4(af[0], af[1], af[2], af[3],
                    qb + rA * 272 + (k16 * 2 + gaof) * 16);
            LDSM_X4(bf[0][0], bf[0][1], bf[1][0], bf[1][1],
                    kb + rB0 * 272 + (k16 * 2 + gbof) * 16);
            LDSM_X4(bf[2][0], bf[2][1], bf[3][0], bf[3][1],
                    kb + rB1 * 272 + (k16 * 2 + gbof) * 16);
#pragma unroll
            for (int ni = 0; ni < 4; ni++) mma16(sc[ni], af, bf[ni]);
        }
#pragma unroll
        for (int ni = 0; ni < 4; ni++) {
            int row = wm * 16 + g4;
            int col = wn * 32 + ni * 8 + t4 * 2;
            ss[row * SP + col]           = sc[ni][0];
            ss[row * SP + col + 1]       = sc[ni][1];
            ss[(row + 8) * SP + col]     = sc[ni][2];
            ss[(row + 8) * SP + col + 1] = sc[ni][3];
        }
    }
    __syncthreads();

    // ---- softmax + relu^2 mix (one warp per row), write attn fp16 (+pads)
    for (int r = warp; r < NTOK; r += 8) {
        int ri = r / 7, ci = r - 7 * ri;
        int j0 = lane;
        int rj0 = j0 / 7, cj0 = j0 - 7 * rj0;
        float x0 = ss[r * SP + j0] + rp[(ri - rj0 + 6) * 13 + (ci - cj0 + 6)];
        int j1 = lane + 32;
        bool v1 = j1 < NTOK;
        float x1 = -1e30f;
        if (v1) {
            int rj1 = j1 / 7, cj1 = j1 - 7 * rj1;
            x1 = ss[r * SP + j1] + rp[(ri - rj1 + 6) * 13 + (ci - cj1 + 6)];
        }
        float m = fmaxf(x0, x1);
#pragma unroll
        for (int o = 16; o > 0; o >>= 1) m = fmaxf(m, __shfl_xor_sync(0xffffffffu, m, o));
        float p0 = __expf(x0 - m);
        float p1 = v1 ? __expf(x1 - m) : 0.f;
        float s = p0 + p1;
#pragma unroll
        for (int o = 16; o > 0; o >>= 1) s += __shfl_xor_sync(0xffffffffu, s, o);
        float inv = 1.f / s;
        float r0 = fmaxf(x0, 0.f), r1 = fmaxf(x1, 0.f);
        at[r * VP + j0] = __float2half_rn(w0 * p0 * inv + w1 * r0 * r0);
        at[r * VP + j1] = v1 ? __float2half_rn(w0 * p1 * inv + w1 * r1 * r1)
                             : __half(0.f);
    }
    for (int idx = tid; idx < (64 - NTOK) * 64; idx += 256) {
        int r = NTOK + idx / 64, c = idx & 63;
        at[r * VP + c] = __half(0.f);
    }
    __syncthreads();

    // ---- O = attn @ v  (M=64, N=128, K=64)
    float oc[8][4];
#pragma unroll
    for (int ni = 0; ni < 8; ni++)
#pragma unroll
        for (int q = 0; q < 4; q++) oc[ni][q] = 0.f;

#pragma unroll
    for (int k16 = 0; k16 < 4; k16++) {
        unsigned af[4], bf[8][2];
        LDSM_X4(af[0], af[1], af[2], af[3],
                ab + rA * 144 + (k16 * 2 + gaof) * 16);
#pragma unroll
        for (int np = 0; np < 4; np++) {
            int rBv = wn * 64 + np * 16 + l7 + (lane >> 4) * 8;
            LDSM_X4(bf[np * 2][0], bf[np * 2][1], bf[np * 2 + 1][0], bf[np * 2 + 1][1],
                    vb + rBv * 144 + (k16 * 2 + gbof) * 16);
        }
#pragma unroll
        for (int ni = 0; ni < 8; ni++) mma16(oc[ni], af, bf[ni]);
    }
    __syncthreads();            // q buffer free; reuse as O staging

#pragma unroll
    for (int ni = 0; ni < 8; ni++) {
        int row = wm * 16 + g4;
        int col = wn * 64 + ni * 8 + t4 * 2;
        qs[row * AP + col]           = __float2half_rn(oc[ni][0]);
        qs[row * AP + col + 1]       = __float2half_rn(oc[ni][1]);
        qs[(row + 8) * AP + col]     = __float2half_rn(oc[ni][2]);
        qs[(row + 8) * AP + col + 1] = __float2half_rn(oc[ni][3]);
    }
    __syncthreads();
    for (int idx = tid; idx < NTOK * 16; idx += 256) {
        int i = idx >> 4, c4 = idx & 15;
        uint4 v = *(uint4*)(qs + i * AP + c4 * 8);
        *(uint4*)(&g_o1[(size_t)(b * NTOK + i) * CD + h * DD + c4 * 8]) = v;
    }
}

// ---------------------------------------------------------------------------
// Launch
// ---------------------------------------------------------------------------
extern "C" void kernel_launch(void* const* d_in, const int* in_sizes, int n_in,
                              void* d_out, int out_size)
{
    const float* x     = (const float*)d_in[0];
    const float* Wq    = (const float*)d_in[1];
    const float* bq    = (const float*)d_in[2];
    const float* Wkv   = (const float*)d_in[3];
    const float* bkv   = (const float*)d_in[4];
    const float* rpb   = (const float*)d_in[5];
    const float* wmix  = (const float*)d_in[6];
    const float* Wproj = (const float*)d_in[7];
    const float* bproj = (const float*)d_in[8];
    float* y = (float*)d_out;

    void *p_xt, *p_qkv, *p_o1, *p_wqkv, *p_bqkv, *p_wp;
    cudaGetSymbolAddress(&p_xt,   g_xt);
    cudaGetSymbolAddress(&p_qkv,  g_qkv);
    cudaGetSymbolAddress(&p_o1,   g_o1);
    cudaGetSymbolAddress(&p_wqkv, g_wqkv);
    cudaGetSymbolAddress(&p_bqkv, g_bqkv);
    cudaGetSymbolAddress(&p_wp,   g_wp);

    cudaFuncSetAttribute(attn_tc, cudaFuncAttributeMaxDynamicSharedMemorySize,
                         ATTN_TC_SMEM);
    cudaFuncSetAttribute(gemm_f16, cudaFuncAttributeMaxDynamicSharedMemorySize,
                         GEMM_SMEM);

    // prep (weights fp16 + bias concat, one launch) + input transpose
    prep_kernel<<<(PREP_TOTAL + 255) / 256, 256>>>(Wq, Wkv, Wproj, bq, bkv);
    transpose_in<<<dim3(BD, CD / 64), 256>>>(x);

    // fused QKV GEMM: N = 3072
    gemm_f16<<<dim3(3 * CD / 128, MM / 128), 256, GEMM_SMEM>>>(
        (const __half*)p_xt, (const __half*)p_wqkv, (const float*)p_bqkv,
        (float*)p_qkv, 3 * CD, 0, 0);

    attn_tc<<<BD * HH, 256, ATTN_TC_SMEM>>>(rpb, wmix);

    // proj GEMM with fused output transpose: writes y (B, C, 7, 7) directly
    gemm_f16<<<dim3(CD / 128, MM / 128), 256, GEMM_SMEM>>>(
        (const __half*)p_o1, (const __half*)p_wp, bproj, y, 0, 0, 1);
}

// round 11
// speedup vs baseline: 2.4834x; 1.0662x over previous
#include <cuda_runtime.h>
#include <cuda_fp16.h>
#include <math.h>
#include <cstdint>

// ---------------------------------------------------------------------------
//   x: (B=512, C=1024, 7, 7) -> N = 49 tokens/window, M = B*N = 25088
//   Q = (xt @ Wq^T + bq) * D^-0.5 ; KV = xt @ Wkv^T + bkv
//   attn = mix(softmax, relu^2)(q k^T + rpb) ; o = attn v ; y = o @ Wproj^T + b
// ---------------------------------------------------------------------------
#define BD   512
#define CD   1024
#define NTOK 49
#define HH   8
#define DD   128
#define MM   (BD * NTOK)          // 25088
#define KK   1024

// Device scratch (allocation-free rule: __device__ globals)
__device__ __half g_xt  [MM * CD];          // (M, C)    xt, fp16
__device__ __half g_qkvh[MM * 3 * CD];      // (M, 3C)   [q | k | v] fp16
__device__ __half g_o1  [MM * CD];          // (M, C)    attn out, fp16
__device__ __half g_wqkv[3 * CD * KK];      // [Wq ; Wkv] fp16
__device__ float  g_bqkv[3 * CD];           // [bq ; bkv]
__device__ __half g_wp  [CD * KK];          // Wproj fp16

// ---------------------------------------------------------------------------
// PTX helpers
// ---------------------------------------------------------------------------
__device__ __forceinline__ void cpa16(unsigned dst, const void* src) {
    asm volatile("cp.async.cg.shared.global [%0], [%1], 16;\n" :: "r"(dst), "l"(src));
}
__device__ __forceinline__ void cpa_commit() {
    asm volatile("cp.async.commit_group;\n");
}
__device__ __forceinline__ void cpa_wait1() {
    asm volatile("cp.async.wait_group 1;\n");
}
#define LDSM_X4(r0, r1, r2, r3, addr) \
    asm volatile("ldmatrix.sync.aligned.m8n8.x4.shared.b16 {%0,%1,%2,%3}, [%4];" \
                 : "=r"(r0), "=r"(r1), "=r"(r2), "=r"(r3) : "r"(addr))

__device__ __forceinline__ void mma16(float* c, const unsigned* a, const unsigned* b) {
    asm volatile(
        "mma.sync.aligned.m16n8k16.row.col.f32.f16.f16.f32 "
        "{%0,%1,%2,%3}, {%4,%5,%6,%7}, {%8,%9}, {%0,%1,%2,%3};"
        : "+f"(c[0]), "+f"(c[1]), "+f"(c[2]), "+f"(c[3])
        : "r"(a[0]), "r"(a[1]), "r"(a[2]), "r"(a[3]), "r"(b[0]), "r"(b[1]));
}

// ---------------------------------------------------------------------------
// Kernel 0: one-shot prep — all weights f32->f16 + bias concat
// ---------------------------------------------------------------------------
#define NQ  (CD * KK / 2)
#define NKV (2 * CD * KK / 2)
#define NP  (CD * KK / 2)
#define PREP_TOTAL (NQ + NKV + NP + 3 * CD)

__global__ __launch_bounds__(256) void prep_kernel(
    const float* __restrict__ Wq, const float* __restrict__ Wkv,
    const float* __restrict__ Wproj,
    const float* __restrict__ bq, const float* __restrict__ bkv)
{
    int i = blockIdx.x * 256 + threadIdx.x;
    if (i < NQ) {
        float2 v = ((const float2*)Wq)[i];
        ((__half2*)g_wqkv)[i] = __floats2half2_rn(v.x, v.y);
    } else if (i < NQ + NKV) {
        int j = i - NQ;
        float2 v = ((const float2*)Wkv)[j];
        ((__half2*)g_wqkv)[NQ + j] = __floats2half2_rn(v.x, v.y);
    } else if (i < NQ + NKV + NP) {
        int j = i - NQ - NKV;
        float2 v = ((const float2*)Wproj)[j];
        ((__half2*)g_wp)[j] = __floats2half2_rn(v.x, v.y);
    } else if (i < PREP_TOTAL) {
        int j = i - NQ - NKV - NP;
        g_bqkv[j] = (j < CD) ? bq[j] : bkv[j - CD];
    }
}

// ---------------------------------------------------------------------------
// Kernel 1: x (B, C, N) -> xt (M, C), fp16, coalesced half2 stores
// ---------------------------------------------------------------------------
__global__ __launch_bounds__(256) void transpose_in(const float* __restrict__ x) {
    __shared__ float t[NTOK][65];
    int b  = blockIdx.x;
    int c0 = blockIdx.y * 64;
    const float* xp = x + (size_t)b * CD * NTOK + (size_t)c0 * NTOK;
    for (int idx = threadIdx.x; idx < 64 * NTOK; idx += 256) {
        int c = idx / NTOK, n = idx - c * NTOK;
        t[n][c] = xp[c * NTOK + n];
    }
    __syncthreads();
    for (int idx = threadIdx.x; idx < NTOK * 32; idx += 256) {
        int n = idx >> 5, p = idx & 31;
        __half2 h = __floats2half2_rn(t[n][2 * p], t[n][2 * p + 1]);
        *(__half2*)&g_xt[(size_t)(b * NTOK + n) * CD + c0 + 2 * p] = h;
    }
}

// ---------------------------------------------------------------------------
// Kernel 2: fp16 GEMM (fp32 acc), tile 128x128x64, 3-stage cp.async,
//   8 warps (2x4), ldmatrix.x4, mma m16n8k16.
//   mode 0: Co  [row, colOff+col] = acc + bias  (fp32)
//   mode 1: y[b, col, n] = acc + bias           (fused output transpose)
//   mode 2: C16 [row, colOff+col] = acc + bias  (fp16 half2 stores)
// ---------------------------------------------------------------------------
#define BK 64
#define NKT (KK / BK)                // 16
#define TILE_B 16384                 // 128 rows * 128 B
#define STAGE_B (2 * TILE_B)
#define GEMM_SMEM (3 * STAGE_B)      // 98304

__global__ __launch_bounds__(256) void gemm_f16(
    const __half* __restrict__ A, const __half* __restrict__ W,
    const float* __restrict__ bias, float* __restrict__ Co,
    __half* __restrict__ C16, int ldc, int colOff, int mode)
{
    extern __shared__ __align__(128) unsigned char gsm[];
    const uint32_t smb = (uint32_t)__cvta_generic_to_shared(gsm);

    const int tid  = threadIdx.x;
    const int m0   = blockIdx.y * 128;
    const int n0   = blockIdx.x * 128;
    const int warp = tid >> 5, lane = tid & 31;
    const int wm = warp >> 2, wn = warp & 3;          // 2 x 4

    const __half* Ab = A + (size_t)m0 * KK;
    const __half* Wb = W + (size_t)n0 * KK;

    const int l7 = lane & 7;
    int rowA[4], rowB[2];
#pragma unroll
    for (int mi = 0; mi < 4; mi++)
        rowA[mi] = wm * 64 + mi * 16 + l7 + ((lane >> 3) & 1) * 8;
#pragma unroll
    for (int p = 0; p < 2; p++)
        rowB[p] = wn * 32 + p * 16 + l7 + (lane >> 4) * 8;
    const int gaof = lane >> 4;
    const int gbof = (lane >> 3) & 1;

    float acc[4][4][4];
#pragma unroll
    for (int mi = 0; mi < 4; mi++)
#pragma unroll
        for (int ni = 0; ni < 4; ni++)
#pragma unroll
            for (int q = 0; q < 4; q++) acc[mi][ni][q] = 0.f;

    auto fill = [&](int buf, int kt) {
        uint32_t baseA = smb + buf * STAGE_B;
        uint32_t baseB = baseA + TILE_B;
        int kof = kt * BK;
#pragma unroll
        for (int i = 0; i < 4; i++) {
            int u = i * 256 + tid;
            int row = u >> 3, g = u & 7;
            uint32_t sw = ((uint32_t)(g ^ (row & 7))) << 4;
            cpa16(baseA + row * 128 + sw, Ab + (size_t)row * KK + kof + g * 8);
            cpa16(baseB + row * 128 + sw, Wb + (size_t)row * KK + kof + g * 8);
        }
    };

    fill(0, 0); cpa_commit();
    fill(1, 1); cpa_commit();

    for (int kt = 0; kt < NKT; kt++) {
        int buf = kt % 3;
        cpa_wait1();
        __syncthreads();

        if (kt + 2 < NKT) fill((kt + 2) % 3, kt + 2);
        cpa_commit();

        uint32_t sA = smb + buf * STAGE_B;
        uint32_t sB = sA + TILE_B;

#pragma unroll
        for (int k16 = 0; k16 < 4; k16++) {
            unsigned af[4][4], bf[4][2];
            uint32_t sga = ((uint32_t)((k16 * 2 + gaof) ^ l7)) << 4;
            uint32_t sgb = ((uint32_t)((k16 * 2 + gbof) ^ l7)) << 4;
#pragma unroll
            for (int mi = 0; mi < 4; mi++)
                LDSM_X4(af[mi][0], af[mi][1], af[mi][2], af[mi][3],
                        sA + rowA[mi] * 128 + sga);
#pragma unroll
            for (int p = 0; p < 2; p++)
                LDSM_X4(bf[p * 2][0], bf[p * 2][1], bf[p * 2 + 1][0], bf[p * 2 + 1][1],
                        sB + rowB[p] * 128 + sgb);
#pragma unroll
            for (int mi = 0; mi < 4; mi++)
#pragma unroll
                for (int ni = 0; ni < 4; ni++)
                    mma16(acc[mi][ni], af[mi], bf[ni]);
        }
    }

    const int g4 = lane >> 2, t4 = lane & 3;
    if (mode == 0) {
#pragma unroll
        for (int mi = 0; mi < 4; mi++) {
#pragma unroll
            for (int ni = 0; ni < 4; ni++) {
                int row = m0 + wm * 64 + mi * 16 + g4;
                int col = n0 + wn * 32 + ni * 8 + t4 * 2;
                float b0 = bias[col], b1 = bias[col + 1];
                float2 v0 = { acc[mi][ni][0] + b0, acc[mi][ni][1] + b1 };
                float2 v1 = { acc[mi][ni][2] + b0, acc[mi][ni][3] + b1 };
                *(float2*)&Co[(size_t)row       * ldc + colOff + col] = v0;
                *(float2*)&Co[(size_t)(row + 8) * ldc + colOff + col] = v1;
            }
        }
    } else if (mode == 2) {
#pragma unroll
        for (int mi = 0; mi < 4; mi++) {
#pragma unroll
            for (int ni = 0; ni < 4; ni++) {
                int row = m0 + wm * 64 + mi * 16 + g4;
                int col = n0 + wn * 32 + ni * 8 + t4 * 2;
                float b0 = bias[col], b1 = bias[col + 1];
                *(__half2*)&C16[(size_t)row * ldc + colOff + col] =
                    __floats2half2_rn(acc[mi][ni][0] + b0, acc[mi][ni][1] + b1);
                *(__half2*)&C16[(size_t)(row + 8) * ldc + colOff + col] =
                    __floats2half2_rn(acc[mi][ni][2] + b0, acc[mi][ni][3] + b1);
            }
        }
    } else {
        // fused output transpose: stage (+bias) into smem [128][129], then
        // write y[b, col, n] with n-contiguous runs
        __syncthreads();                    // pipeline buffers now free
        float* st = (float*)gsm;
#pragma unroll
        for (int mi = 0; mi < 4; mi++) {
#pragma unroll
            for (int ni = 0; ni < 4; ni++) {
                int row = wm * 64 + mi * 16 + g4;
                int col = wn * 32 + ni * 8 + t4 * 2;
                float b0 = bias[n0 + col], b1 = bias[n0 + col + 1];
                st[row * 129 + col]           = acc[mi][ni][0] + b0;
                st[row * 129 + col + 1]       = acc[mi][ni][1] + b1;
                st[(row + 8) * 129 + col]     = acc[mi][ni][2] + b0;
                st[(row + 8) * 129 + col + 1] = acc[mi][ni][3] + b1;
            }
        }
        __syncthreads();
        for (int idx = tid; idx < 128 * 128; idx += 256) {
            int c = idx >> 7, r = idx & 127;
            int grow = m0 + r;
            int b = grow / NTOK, n = grow - b * NTOK;
            Co[(size_t)b * CD * NTOK + (size_t)(n0 + c) * NTOK + n] = st[r * 129 + c];
        }
    }
}

// ---------------------------------------------------------------------------
// Kernel 3: tensor-core windowed attention per (b, h). 256 threads, 4096 blocks.
//   fp16 qkv source; smem 71.4KB -> 3 CTAs/SM.
//   Aliasing: attn fp16 matrix reuses qs (dead after S mma); O staging reuses ks.
// ---------------------------------------------------------------------------
#define AP 136            // halves per q/k row (272 B)
#define VP 72             // halves per vT/attn row (144 B)
#define SP 68             // floats per S row (272 B)
#define ATTN_TC_SMEM (2 * 64 * AP * 2 + 128 * VP * 2 + 64 * SP * 4 + 704)

__global__ __launch_bounds__(256) void attn_tc(const float* __restrict__ rpb_table,
                                               const float* __restrict__ w_mix)
{
    extern __shared__ __align__(16) unsigned char asmm[];
    __half* qs = (__half*)asmm;                 // 64 x AP ; later: attn (VP pitch)
    __half* ks = qs + 64 * AP;                  // 64 x AP ; later: O staging
    __half* vt = ks + 64 * AP;                  // 128 x VP (vT: row=d, col=j)
    float*  ss = (float*)(vt + 128 * VP);       // 64 x SP
    float*  rp = ss + 64 * SP;                  // 169

    const int bh = blockIdx.x;
    const int b = bh >> 3, h = bh & 7;
    const int tid = threadIdx.x;
    const int warp = tid >> 5, lane = tid & 31;

    float wa = w_mix[0], wb = w_mix[1];
    float wmx = fmaxf(wa, wb);
    float ea = __expf(wa - wmx), eb = __expf(wb - wmx);
    float wden = 1.f / (ea + eb);
    float w0 = ea * wden, w1 = eb * wden;

    const float scale = 0.08838834764831845f;   // 128^-0.5 (applied to S)
    size_t base = (size_t)(b * NTOK) * (3 * CD) + h * DD;

    // ---- load q, k, vT from fp16 qkv (coalesced 2B reads)
    const __half hz = __half(0.f);
    for (int idx = tid; idx < 64 * DD; idx += 256) {
        int i = idx >> 7, d = idx & 127;
        __half qv = hz, kv = hz;
        if (i < NTOK) {
            size_t r = base + (size_t)i * (3 * CD) + d;
            qv = g_qkvh[r];
            kv = g_qkvh[r + CD];
        }
        qs[i * AP + d] = qv;
        ks[i * AP + d] = kv;
    }
    for (int idx = tid; idx < 64 * DD; idx += 256) {
        int j = idx >> 7, d = idx & 127;
        vt[d * VP + j] = (j < NTOK) ? g_qkvh[base + (size_t)j * (3 * CD) + 2 * CD + d]
                                    : hz;
    }
    for (int idx = tid; idx < 169; idx += 256) rp[idx] = rpb_table[idx * HH + h];
    __syncthreads();

    const uint32_t qb = (uint32_t)__cvta_generic_to_shared(qs);
    const uint32_t kb = (uint32_t)__cvta_generic_to_shared(ks);
    const uint32_t vb = (uint32_t)__cvta_generic_to_shared(vt);

    const int wm = warp >> 1, wn = warp & 1;    // 4 x 2
    const int l7 = lane & 7;
    const int rA  = wm * 16 + l7 + ((lane >> 3) & 1) * 8;
    const int gaof = lane >> 4, gbof = (lane >> 3) & 1;
    const int g4 = lane >> 2, t4 = lane & 3;

    // ---- S = scale * q k^T  (M=64, N=64, K=128)
    {
        float sc[4][4];
#pragma unroll
        for (int ni = 0; ni < 4; ni++)
#pragma unroll
            for (int q = 0; q < 4; q++) sc[ni][q] = 0.f;

        const int rB0 = wn * 32 + l7 + (lane >> 4) * 8;
        const int rB1 = rB0 + 16;
#pragma unroll
        for (int k16 = 0; k16 < 8; k16++) {
            unsigned af[4], bf[4][2];
            LDSM_X4(af[0], af[1], af[2], af[3],
                    qb + rA * 272 + (k16 * 2 + gaof) * 16);
            LDSM_X4(bf[0][0], bf[0][1], bf[1][0], bf[1][1],
                    kb + rB0 * 272 + (k16 * 2 + gbof) * 16);
            LDSM_X4(bf[2][0], bf[2][1], bf[3][0], bf[3][1],
                    kb + rB1 * 272 + (k16 * 2 + gbof) * 16);
#pragma unroll
            for (int ni = 0; ni < 4; ni++) mma16(sc[ni], af, bf[ni]);
        }
#pragma unroll
        for (int ni = 0; ni < 4; ni++) {
            int row = wm * 16 + g4;
            int col = wn * 32 + ni * 8 + t4 * 2;
            ss[row * SP + col]           = sc[ni][0] * scale;
            ss[row * SP + col + 1]       = sc[ni][1] * scale;
            ss[(row + 8) * SP + col]     = sc[ni][2] * scale;
            ss[(row + 8) * SP + col + 1] = sc[ni][3] * scale;
        }
    }
    __syncthreads();                // qs now dead -> reuse as attn buffer

    __half* at = qs;                // 64 x VP (fits in 64 x AP region)
    const uint32_t ab = qb;

    // ---- softmax + relu^2 mix (one warp per row), write attn fp16 (+pads)
    for (int r = warp; r < NTOK; r += 8) {
        int ri = r / 7, ci = r - 7 * ri;
        int j0 = lane;
        int rj0 = j0 / 7, cj0 = j0 - 7 * rj0;
        float x0 = ss[r * SP + j0] + rp[(ri - rj0 + 6) * 13 + (ci - cj0 + 6)];
        int j1 = lane + 32;
        bool v1 = j1 < NTOK;
        float x1 = -1e30f;
        if (v1) {
            int rj1 = j1 / 7, cj1 = j1 - 7 * rj1;
            x1 = ss[r * SP + j1] + rp[(ri - rj1 + 6) * 13 + (ci - cj1 + 6)];
        }
        float m = fmaxf(x0, x1);
#pragma unroll
        for (int o = 16; o > 0; o >>= 1) m = fmaxf(m, __shfl_xor_sync(0xffffffffu, m, o));
        float p0 = __expf(x0 - m);
        float p1 = v1 ? __expf(x1 - m) : 0.f;
        float s = p0 + p1;
#pragma unroll
        for (int o = 16; o > 0; o >>= 1) s += __shfl_xor_sync(0xffffffffu, s, o);
        float inv = 1.f / s;
        float r0 = fmaxf(x0, 0.f), r1 = fmaxf(x1, 0.f);
        at[r * VP + j0] = __float2half_rn(w0 * p0 * inv + w1 * r0 * r0);
        at[r * VP + j1] = v1 ? __float2half_rn(w0 * p1 * inv + w1 * r1 * r1)
                             : hz;
    }
    for (int idx = tid; idx < (64 - NTOK) * 64; idx += 256) {
        int r = NTOK + idx / 64, c = idx & 63;
        at[r * VP + c] = hz;
    }
    __syncthreads();

    // ---- O = attn @ v  (M=64, N=128, K=64)
    float oc[8][4];
#pragma unroll
    for (int ni = 0; ni < 8; ni++)
#pragma unroll
        for (int q = 0; q < 4; q++) oc[ni][q] = 0.f;

#pragma unroll
    for (int k16 = 0; k16 < 4; k16++) {
        unsigned af[4], bf[8][2];
        LDSM_X4(af[0], af[1], af[2], af[3],
                ab + rA * 144 + (k16 * 2 + gaof) * 16);
#pragma unroll
        for (int np = 0; np < 4; np++) {
            int rBv = wn * 64 + np * 16 + l7 + (lane >> 4) * 8;
            LDSM_X4(bf[np * 2][0], bf[np * 2][1], bf[np * 2 + 1][0], bf[np * 2 + 1][1],
                    vb + rBv * 144 + (k16 * 2 + gbof) * 16);
        }
#pragma unroll
        for (int ni = 0; ni < 8; ni++) mma16(oc[ni], af, bf[ni]);
    }
    __syncthreads();            // ks free; reuse as O staging

#pragma unroll
    for (int ni = 0; ni < 8; ni++) {
        int row = wm * 16 + g4;
        int col = wn * 64 + ni * 8 + t4 * 2;
        ks[row * AP + col]           = __float2half_rn(oc[ni][0]);
        ks[row * AP + col + 1]       = __float2half_rn(oc[ni][1]);
        ks[(row + 8) * AP + col]     = __float2half_rn(oc[ni][2]);
        ks[(row + 8) * AP + col + 1] = __float2half_rn(oc[ni][3]);
    }
    __syncthreads();
    for (int idx = tid; idx < NTOK * 16; idx += 256) {
        int i = idx >> 4, c4 = idx & 15;
        uint4 v = *(uint4*)(ks + i * AP + c4 * 8);
        *(uint4*)(&g_o1[(size_t)(b * NTOK + i) * CD + h * DD + c4 * 8]) = v;
    }
}

// ---------------------------------------------------------------------------
// Launch
// ---------------------------------------------------------------------------
extern "C" void kernel_launch(void* const* d_in, const int* in_sizes, int n_in,
                              void* d_out, int out_size)
{
    const float* x     = (const float*)d_in[0];
    const float* Wq    = (const float*)d_in[1];
    const float* bq    = (const float*)d_in[2];
    const float* Wkv   = (const float*)d_in[3];
    const float* bkv   = (const float*)d_in[4];
    const float* rpb   = (const float*)d_in[5];
    const float* wmix  = (const float*)d_in[6];
    const float* Wproj = (const float*)d_in[7];
    const float* bproj = (const float*)d_in[8];
    float* y = (float*)d_out;

    void *p_xt, *p_qkvh, *p_o1, *p_wqkv, *p_bqkv, *p_wp;
    cudaGetSymbolAddress(&p_xt,   g_xt);
    cudaGetSymbolAddress(&p_qkvh, g_qkvh);
    cudaGetSymbolAddress(&p_o1,   g_o1);
    cudaGetSymbolAddress(&p_wqkv, g_wqkv);
    cudaGetSymbolAddress(&p_bqkv, g_bqkv);
    cudaGetSymbolAddress(&p_wp,   g_wp);

    cudaFuncSetAttribute(attn_tc, cudaFuncAttributeMaxDynamicSharedMemorySize,
                         ATTN_TC_SMEM);
    cudaFuncSetAttribute(gemm_f16, cudaFuncAttributeMaxDynamicSharedMemorySize,
                         GEMM_SMEM);

    // prep (weights fp16 + bias concat, one launch) + input transpose
    prep_kernel<<<(PREP_TOTAL + 255) / 256, 256>>>(Wq, Wkv, Wproj, bq, bkv);
    transpose_in<<<dim3(BD, CD / 64), 256>>>(x);

    // fused QKV GEMM: N = 3072, fp16 output
    gemm_f16<<<dim3(3 * CD / 128, MM / 128), 256, GEMM_SMEM>>>(
        (const __half*)p_xt, (const __half*)p_wqkv, (const float*)p_bqkv,
        nullptr, (__half*)p_qkvh, 3 * CD, 0, 2);

    attn_tc<<<BD * HH, 256, ATTN_TC_SMEM>>>(rpb, wmix);

    // proj GEMM with fused output transpose: writes y (B, C, 7, 7) directly
    gemm_f16<<<dim3(CD / 128, MM / 128), 256, GEMM_SMEM>>>(
        (const __half*)p_o1, (const __half*)p_wp, bproj, y, nullptr, 0, 0, 1);
}

// round 12
// speedup vs baseline: 2.4897x; 1.0026x over previous
#include <cuda_runtime.h>
#include <cuda_fp16.h>
#include <math.h>
#include <cstdint>

// ---------------------------------------------------------------------------
//   x: (B=512, C=1024, 7, 7) -> N = 49 tokens/window, M = B*N = 25088
//   Q = (xt @ Wq^T + bq) * D^-0.5 ; KV = xt @ Wkv^T + bkv
//   attn = mix(softmax, relu^2)(q k^T + rpb) ; o = attn v ; y = o @ Wproj^T + b
// ---------------------------------------------------------------------------
#define BD   512
#define CD   1024
#define NTOK 49
#define HH   8
#define DD   128
#define MM   (BD * NTOK)          // 25088
#define KK   1024

// Device scratch (allocation-free rule: __device__ globals)
__device__ __half g_xt  [MM * CD];          // (M, C)    xt, fp16
__device__ __half g_qkvh[MM * 3 * CD];      // (M, 3C)   [q | k | v] fp16
__device__ __half g_o1  [MM * CD];          // (M, C)    attn out, fp16
__device__ __half g_wqkv[3 * CD * KK];      // [Wq ; Wkv] fp16
__device__ float  g_bqkv[3 * CD];           // [bq ; bkv]
__device__ __half g_wp  [CD * KK];          // Wproj fp16

// ---------------------------------------------------------------------------
// PTX helpers
// ---------------------------------------------------------------------------
__device__ __forceinline__ void cpa16(unsigned dst, const void* src) {
    asm volatile("cp.async.cg.shared.global [%0], [%1], 16;\n" :: "r"(dst), "l"(src));
}
__device__ __forceinline__ void cpa_commit() {
    asm volatile("cp.async.commit_group;\n");
}
__device__ __forceinline__ void cpa_wait1() {
    asm volatile("cp.async.wait_group 1;\n");
}
#define LDSM_X4(r0, r1, r2, r3, addr) \
    asm volatile("ldmatrix.sync.aligned.m8n8.x4.shared.b16 {%0,%1,%2,%3}, [%4];" \
                 : "=r"(r0), "=r"(r1), "=r"(r2), "=r"(r3) : "r"(addr))

__device__ __forceinline__ void mma16(float* c, const unsigned* a, const unsigned* b) {
    asm volatile(
        "mma.sync.aligned.m16n8k16.row.col.f32.f16.f16.f32 "
        "{%0,%1,%2,%3}, {%4,%5,%6,%7}, {%8,%9}, {%0,%1,%2,%3};"
        : "+f"(c[0]), "+f"(c[1]), "+f"(c[2]), "+f"(c[3])
        : "r"(a[0]), "r"(a[1]), "r"(a[2]), "r"(a[3]), "r"(b[0]), "r"(b[1]));
}

// ---------------------------------------------------------------------------
// Kernel 0: one-shot prep — all weights f32->f16 + bias concat
// ---------------------------------------------------------------------------
#define NQ  (CD * KK / 2)
#define NKV (2 * CD * KK / 2)
#define NP  (CD * KK / 2)
#define PREP_TOTAL (NQ + NKV + NP + 3 * CD)

__global__ __launch_bounds__(256) void prep_kernel(
    const float* __restrict__ Wq, const float* __restrict__ Wkv,
    const float* __restrict__ Wproj,
    const float* __restrict__ bq, const float* __restrict__ bkv)
{
    int i = blockIdx.x * 256 + threadIdx.x;
    if (i < NQ) {
        float2 v = ((const float2*)Wq)[i];
        ((__half2*)g_wqkv)[i] = __floats2half2_rn(v.x, v.y);
    } else if (i < NQ + NKV) {
        int j = i - NQ;
        float2 v = ((const float2*)Wkv)[j];
        ((__half2*)g_wqkv)[NQ + j] = __floats2half2_rn(v.x, v.y);
    } else if (i < NQ + NKV + NP) {
        int j = i - NQ - NKV;
        float2 v = ((const float2*)Wproj)[j];
        ((__half2*)g_wp)[j] = __floats2half2_rn(v.x, v.y);
    } else if (i < PREP_TOTAL) {
        int j = i - NQ - NKV - NP;
        g_bqkv[j] = (j < CD) ? bq[j] : bkv[j - CD];
    }
}

// ---------------------------------------------------------------------------
// Kernel 1: x (B, C, N) -> xt (M, C), fp16, coalesced half2 stores
// ---------------------------------------------------------------------------
__global__ __launch_bounds__(256) void transpose_in(const float* __restrict__ x) {
    __shared__ float t[NTOK][65];
    int b  = blockIdx.x;
    int c0 = blockIdx.y * 64;
    const float* xp = x + (size_t)b * CD * NTOK + (size_t)c0 * NTOK;
    for (int idx = threadIdx.x; idx < 64 * NTOK; idx += 256) {
        int c = idx / NTOK, n = idx - c * NTOK;
        t[n][c] = xp[c * NTOK + n];
    }
    __syncthreads();
    for (int idx = threadIdx.x; idx < NTOK * 32; idx += 256) {
        int n = idx >> 5, p = idx & 31;
        __half2 h = __floats2half2_rn(t[n][2 * p], t[n][2 * p + 1]);
        *(__half2*)&g_xt[(size_t)(b * NTOK + n) * CD + c0 + 2 * p] = h;
    }
}

// ---------------------------------------------------------------------------
// Kernel 2: fp16 GEMM (fp32 acc), tile 128x128x64, 3-stage cp.async,
//   8 warps (2x4), ldmatrix.x4, mma m16n8k16.
//   mode 0: Co  [row, colOff+col] = acc + bias  (fp32)
//   mode 1: y[b, col, n] = acc + bias           (fused output transpose)
//   mode 2: C16 [row, colOff+col] = acc + bias  (fp16 half2 stores)
// ---------------------------------------------------------------------------
#define BK 64
#define NKT (KK / BK)                // 16
#define TILE_B 16384                 // 128 rows * 128 B
#define STAGE_B (2 * TILE_B)
#define GEMM_SMEM (3 * STAGE_B)      // 98304

__global__ __launch_bounds__(256) void gemm_f16(
    const __half* __restrict__ A, const __half* __restrict__ W,
    const float* __restrict__ bias, float* __restrict__ Co,
    __half* __restrict__ C16, int ldc, int colOff, int mode)
{
    extern __shared__ __align__(128) unsigned char gsm[];
    const uint32_t smb = (uint32_t)__cvta_generic_to_shared(gsm);

    const int tid  = threadIdx.x;
    const int m0   = blockIdx.y * 128;
    const int n0   = blockIdx.x * 128;
    const int warp = tid >> 5, lane = tid & 31;
    const int wm = warp >> 2, wn = warp & 3;          // 2 x 4

    const __half* Ab = A + (size_t)m0 * KK;
    const __half* Wb = W + (size_t)n0 * KK;

    const int l7 = lane & 7;
    int rowA[4], rowB[2];
#pragma unroll
    for (int mi = 0; mi < 4; mi++)
        rowA[mi] = wm * 64 + mi * 16 + l7 + ((lane >> 3) & 1) * 8;
#pragma unroll
    for (int p = 0; p < 2; p++)
        rowB[p] = wn * 32 + p * 16 + l7 + (lane >> 4) * 8;
    const int gaof = lane >> 4;
    const int gbof = (lane >> 3) & 1;

    float acc[4][4][4];
#pragma unroll
    for (int mi = 0; mi < 4; mi++)
#pragma unroll
        for (int ni = 0; ni < 4; ni++)
#pragma unroll
            for (int q = 0; q < 4; q++) acc[mi][ni][q] = 0.f;

    auto fill = [&](int buf, int kt) {
        uint32_t baseA = smb + buf * STAGE_B;
        uint32_t baseB = baseA + TILE_B;
        int kof = kt * BK;
#pragma unroll
        for (int i = 0; i < 4; i++) {
            int u = i * 256 + tid;
            int row = u >> 3, g = u & 7;
            uint32_t sw = ((uint32_t)(g ^ (row & 7))) << 4;
            cpa16(baseA + row * 128 + sw, Ab + (size_t)row * KK + kof + g * 8);
            cpa16(baseB + row * 128 + sw, Wb + (size_t)row * KK + kof + g * 8);
        }
    };

    fill(0, 0); cpa_commit();
    fill(1, 1); cpa_commit();

    for (int kt = 0; kt < NKT; kt++) {
        int buf = kt % 3;
        cpa_wait1();
        __syncthreads();

        if (kt + 2 < NKT) fill((kt + 2) % 3, kt + 2);
        cpa_commit();

        uint32_t sA = smb + buf * STAGE_B;
        uint32_t sB = sA + TILE_B;

#pragma unroll
        for (int k16 = 0; k16 < 4; k16++) {
            unsigned af[4][4], bf[4][2];
            uint32_t sga = ((uint32_t)((k16 * 2 + gaof) ^ l7)) << 4;
            uint32_t sgb = ((uint32_t)((k16 * 2 + gbof) ^ l7)) << 4;
#pragma unroll
            for (int mi = 0; mi < 4; mi++)
                LDSM_X4(af[mi][0], af[mi][1], af[mi][2], af[mi][3],
                        sA + rowA[mi] * 128 + sga);
#pragma unroll
            for (int p = 0; p < 2; p++)
                LDSM_X4(bf[p * 2][0], bf[p * 2][1], bf[p * 2 + 1][0], bf[p * 2 + 1][1],
                        sB + rowB[p] * 128 + sgb);
#pragma unroll
            for (int mi = 0; mi < 4; mi++)
#pragma unroll
                for (int ni = 0; ni < 4; ni++)
                    mma16(acc[mi][ni], af[mi], bf[ni]);
        }
    }

    const int g4 = lane >> 2, t4 = lane & 3;
    if (mode == 0) {
#pragma unroll
        for (int mi = 0; mi < 4; mi++) {
#pragma unroll
            for (int ni = 0; ni < 4; ni++) {
                int row = m0 + wm * 64 + mi * 16 + g4;
                int col = n0 + wn * 32 + ni * 8 + t4 * 2;
                float b0 = bias[col], b1 = bias[col + 1];
                float2 v0 = { acc[mi][ni][0] + b0, acc[mi][ni][1] + b1 };
                float2 v1 = { acc[mi][ni][2] + b0, acc[mi][ni][3] + b1 };
                *(float2*)&Co[(size_t)row       * ldc + colOff + col] = v0;
                *(float2*)&Co[(size_t)(row + 8) * ldc + colOff + col] = v1;
            }
        }
    } else if (mode == 2) {
#pragma unroll
        for (int mi = 0; mi < 4; mi++) {
#pragma unroll
            for (int ni = 0; ni < 4; ni++) {
                int row = m0 + wm * 64 + mi * 16 + g4;
                int col = n0 + wn * 32 + ni * 8 + t4 * 2;
                float b0 = bias[col], b1 = bias[col + 1];
                *(__half2*)&C16[(size_t)row * ldc + colOff + col] =
                    __floats2half2_rn(acc[mi][ni][0] + b0, acc[mi][ni][1] + b1);
                *(__half2*)&C16[(size_t)(row + 8) * ldc + colOff + col] =
                    __floats2half2_rn(acc[mi][ni][2] + b0, acc[mi][ni][3] + b1);
            }
        }
    } else {
        // fused output transpose: stage (+bias) into smem [128][129], then
        // write y[b, col, n] with n-contiguous runs
        __syncthreads();                    // pipeline buffers now free
        float* st = (float*)gsm;
#pragma unroll
        for (int mi = 0; mi < 4; mi++) {
#pragma unroll
            for (int ni = 0; ni < 4; ni++) {
                int row = wm * 64 + mi * 16 + g4;
                int col = wn * 32 + ni * 8 + t4 * 2;
                float b0 = bias[n0 + col], b1 = bias[n0 + col + 1];
                st[row * 129 + col]           = acc[mi][ni][0] + b0;
                st[row * 129 + col + 1]       = acc[mi][ni][1] + b1;
                st[(row + 8) * 129 + col]     = acc[mi][ni][2] + b0;
                st[(row + 8) * 129 + col + 1] = acc[mi][ni][3] + b1;
            }
        }
        __syncthreads();
        for (int idx = tid; idx < 128 * 128; idx += 256) {
            int c = idx >> 7, r = idx & 127;
            int grow = m0 + r;
            int b = grow / NTOK, n = grow - b * NTOK;
            Co[(size_t)b * CD * NTOK + (size_t)(n0 + c) * NTOK + n] = st[r * 129 + c];
        }
    }
}

// ---------------------------------------------------------------------------
// Kernel 3: tensor-core windowed attention per (b, h). 256 threads, 4096 blocks.
//   fp16 qkv source; smem 71.4KB -> 3 CTAs/SM.
//   Aliasing: attn fp16 matrix reuses qs (dead after S mma); O staging reuses ks.
// ---------------------------------------------------------------------------
#define AP 136            // halves per q/k row (272 B)
#define VP 72             // halves per vT/attn row (144 B)
#define SP 68             // floats per S row (272 B)
#define ATTN_TC_SMEM (2 * 64 * AP * 2 + 128 * VP * 2 + 64 * SP * 4 + 704)

__global__ __launch_bounds__(256) void attn_tc(const float* __restrict__ rpb_table,
                                               const float* __restrict__ w_mix)
{
    extern __shared__ __align__(16) unsigned char asmm[];
    __half* qs = (__half*)asmm;                 // 64 x AP ; later: attn (VP pitch)
    __half* ks = qs + 64 * AP;                  // 64 x AP ; later: O staging
    __half* vt = ks + 64 * AP;                  // 128 x VP (vT: row=d, col=j)
    float*  ss = (float*)(vt + 128 * VP);       // 64 x SP
    float*  rp = ss + 64 * SP;                  // 169

    const int bh = blockIdx.x;
    const int b = bh >> 3, h = bh & 7;
    const int tid = threadIdx.x;
    const int warp = tid >> 5, lane = tid & 31;

    float wa = w_mix[0], wb = w_mix[1];
    float wmx = fmaxf(wa, wb);
    float ea = __expf(wa - wmx), eb = __expf(wb - wmx);
    float wden = 1.f / (ea + eb);
    float w0 = ea * wden, w1 = eb * wden;

    const float scale = 0.08838834764831845f;   // 128^-0.5 (applied to S)
    size_t base = (size_t)(b * NTOK) * (3 * CD) + h * DD;

    // ---- load q, k, vT from fp16 qkv (coalesced 2B reads)
    const __half hz = __half(0.f);
    for (int idx = tid; idx < 64 * DD; idx += 256) {
        int i = idx >> 7, d = idx & 127;
        __half qv = hz, kv = hz;
        if (i < NTOK) {
            size_t r = base + (size_t)i * (3 * CD) + d;
            qv = g_qkvh[r];
            kv = g_qkvh[r + CD];
        }
        qs[i * AP + d] = qv;
        ks[i * AP + d] = kv;
    }
    for (int idx = tid; idx < 64 * DD; idx += 256) {
        int j = idx >> 7, d = idx & 127;
        vt[d * VP + j] = (j < NTOK) ? g_qkvh[base + (size_t)j * (3 * CD) + 2 * CD + d]
                                    : hz;
    }
    for (int idx = tid; idx < 169; idx += 256) rp[idx] = rpb_table[idx * HH + h];
    __syncthreads();

    const uint32_t qb = (uint32_t)__cvta_generic_to_shared(qs);
    const uint32_t kb = (uint32_t)__cvta_generic_to_shared(ks);
    const uint32_t vb = (uint32_t)__cvta_generic_to_shared(vt);

    const int wm = warp >> 1, wn = warp & 1;    // 4 x 2
    const int l7 = lane & 7;
    const int rA  = wm * 16 + l7 + ((lane >> 3) & 1) * 8;
    const int gaof = lane >> 4, gbof = (lane >> 3) & 1;
    const int g4 = lane >> 2, t4 = lane & 3;

    // ---- S = scale * q k^T  (M=64, N=64, K=128)
    {
        float sc[4][4];
#pragma unroll
        for (int ni = 0; ni < 4; ni++)
#pragma unroll
            for (int q = 0; q < 4; q++) sc[ni][q] = 0.f;

        const int rB0 = wn * 32 + l7 + (lane >> 4) * 8;
        const int rB1 = rB0 + 16;
#pragma unroll
        for (int k16 = 0; k16 < 8; k16++) {
            unsigned af[4], bf[4][2];
            LDSM_X4(af[0], af[1], af[2], af[3],
                    qb + rA * 272 + (k16 * 2 + gaof) * 16);
            LDSM_X4(bf[0][0], bf[0][1], bf[1][0], bf[1][1],
                    kb + rB0 * 272 + (k16 * 2 + gbof) * 16);
            LDSM_X4(bf[2][0], bf[2][1], bf[3][0], bf[3][1],
                    kb + rB1 * 272 + (k16 * 2 + gbof) * 16);
#pragma unroll
            for (int ni = 0; ni < 4; ni++) mma16(sc[ni], af, bf[ni]);
        }
#pragma unroll
        for (int ni = 0; ni < 4; ni++) {
            int row = wm * 16 + g4;
            int col = wn * 32 + ni * 8 + t4 * 2;
            ss[row * SP + col]           = sc[ni][0] * scale;
            ss[row * SP + col + 1]       = sc[ni][1] * scale;
            ss[(row + 8) * SP + col]     = sc[ni][2] * scale;
            ss[(row + 8) * SP + col + 1] = sc[ni][3] * scale;
        }
    }
    __syncthreads();                // qs now dead -> reuse as attn buffer

    __half* at = qs;                // 64 x VP (fits in 64 x AP region)
    const uint32_t ab = qb;

    // ---- softmax + relu^2 mix (one warp per row), write attn fp16 (+pads)
    for (int r = warp; r < NTOK; r += 8) {
        int ri = r / 7, ci = r - 7 * ri;
        int j0 = lane;
        int rj0 = j0 / 7, cj0 = j0 - 7 * rj0;
        float x0 = ss[r * SP + j0] + rp[(ri - rj0 + 6) * 13 + (ci - cj0 + 6)];
        int j1 = lane + 32;
        bool v1 = j1 < NTOK;
        float x1 = -1e30f;
        if (v1) {
            int rj1 = j1 / 7, cj1 = j1 - 7 * rj1;
            x1 = ss[r * SP + j1] + rp[(ri - rj1 + 6) * 13 + (ci - cj1 + 6)];
        }
        float m = fmaxf(x0, x1);
#pragma unroll
        for (int o = 16; o > 0; o >>= 1) m = fmaxf(m, __shfl_xor_sync(0xffffffffu, m, o));
        float p0 = __expf(x0 - m);
        float p1 = v1 ? __expf(x1 - m) : 0.f;
        float s = p0 + p1;
#pragma unroll
        for (int o = 16; o > 0; o >>= 1) s += __shfl_xor_sync(0xffffffffu, s, o);
        float inv = 1.f / s;
        float r0 = fmaxf(x0, 0.f), r1 = fmaxf(x1, 0.f);
        at[r * VP + j0] = __float2half_rn(w0 * p0 * inv + w1 * r0 * r0);
        at[r * VP + j1] = v1 ? __float2half_rn(w0 * p1 * inv + w1 * r1 * r1)
                             : hz;
    }
    for (int idx = tid; idx < (64 - NTOK) * 64; idx += 256) {
        int r = NTOK + idx / 64, c = idx & 63;
        at[r * VP + c] = hz;
    }
    __syncthreads();

    // ---- O = attn @ v  (M=64, N=128, K=64)
    float oc[8][4];
#pragma unroll
    for (int ni = 0; ni < 8; ni++)
#pragma unroll
        for (int q = 0; q < 4; q++) oc[ni][q] = 0.f;

#pragma unroll
    for (int k16 = 0; k16 < 4; k16++) {
        unsigned af[4], bf[8][2];
        LDSM_X4(af[0], af[1], af[2], af[3],
                ab + rA * 144 + (k16 * 2 + gaof) * 16);
#pragma unroll
        for (int np = 0; np < 4; np++) {
            int rBv = wn * 64 + np * 16 + l7 + (lane >> 4) * 8;
            LDSM_X4(bf[np * 2][0], bf[np * 2][1], bf[np * 2 + 1][0], bf[np * 2 + 1][1],
                    vb + rBv * 144 + (k16 * 2 + gbof) * 16);
        }
#pragma unroll
        for (int ni = 0; ni < 8; ni++) mma16(oc[ni], af, bf[ni]);
    }
    __syncthreads();            // ks free; reuse as O staging

#pragma unroll
    for (int ni = 0; ni < 8; ni++) {
        int row = wm * 16 + g4;
        int col = wn * 64 + ni * 8 + t4 * 2;
        ks[row * AP + col]           = __float2half_rn(oc[ni][0]);
        ks[row * AP + col + 1]       = __float2half_rn(oc[ni][1]);
        ks[(row + 8) * AP + col]     = __float2half_rn(oc[ni][2]);
        ks[(row + 8) * AP + col + 1] = __float2half_rn(oc[ni][3]);
    }
    __syncthreads();
    for (int idx = tid; idx < NTOK * 16; idx += 256) {
        int i = idx >> 4, c4 = idx & 15;
        uint4 v = *(uint4*)(ks + i * AP + c4 * 8);
        *(uint4*)(&g_o1[(size_t)(b * NTOK + i) * CD + h * DD + c4 * 8]) = v;
    }
}

// ---------------------------------------------------------------------------
// Launch
// ---------------------------------------------------------------------------
extern "C" void kernel_launch(void* const* d_in, const int* in_sizes, int n_in,
                              void* d_out, int out_size)
{
    const float* x     = (const float*)d_in[0];
    const float* Wq    = (const float*)d_in[1];
    const float* bq    = (const float*)d_in[2];
    const float* Wkv   = (const float*)d_in[3];
    const float* bkv   = (const float*)d_in[4];
    const float* rpb   = (const float*)d_in[5];
    const float* wmix  = (const float*)d_in[6];
    const float* Wproj = (const float*)d_in[7];
    const float* bproj = (const float*)d_in[8];
    float* y = (float*)d_out;

    void *p_xt, *p_qkvh, *p_o1, *p_wqkv, *p_bqkv, *p_wp;
    cudaGetSymbolAddress(&p_xt,   g_xt);
    cudaGetSymbolAddress(&p_qkvh, g_qkvh);
    cudaGetSymbolAddress(&p_o1,   g_o1);
    cudaGetSymbolAddress(&p_wqkv, g_wqkv);
    cudaGetSymbolAddress(&p_bqkv, g_bqkv);
    cudaGetSymbolAddress(&p_wp,   g_wp);

    cudaFuncSetAttribute(attn_tc, cudaFuncAttributeMaxDynamicSharedMemorySize,
                         ATTN_TC_SMEM);
    cudaFuncSetAttribute(gemm_f16, cudaFuncAttributeMaxDynamicSharedMemorySize,
                         GEMM_SMEM);

    // prep (weights fp16 + bias concat, one launch) + input transpose
    prep_kernel<<<(PREP_TOTAL + 255) / 256, 256>>>(Wq, Wkv, Wproj, bq, bkv);
    transpose_in<<<dim3(BD, CD / 64), 256>>>(x);

    // fused QKV GEMM: N = 3072, fp16 output
    gemm_f16<<<dim3(3 * CD / 128, MM / 128), 256, GEMM_SMEM>>>(
        (const __half*)p_xt, (const __half*)p_wqkv, (const float*)p_bqkv,
        nullptr, (__half*)p_qkvh, 3 * CD, 0, 2);

    attn_tc<<<BD * HH, 256, ATTN_TC_SMEM>>>(rpb, wmix);

    // proj GEMM with fused output transpose: writes y (B, C, 7, 7) directly
    gemm_f16<<<dim3(CD / 128, MM / 128), 256, GEMM_SMEM>>>(
        (const __half*)p_o1, (const __half*)p_wp, bproj, y, nullptr, 0, 0, 1);
}

// round 14
// speedup vs baseline: 2.8536x; 1.1461x over previous
#include <cuda_runtime.h>
#include <cuda_fp16.h>
#include <math.h>
#include <cstdint>

// ---------------------------------------------------------------------------
//   x: (B=512, C=1024, 7, 7) -> N = 49 tokens/window, M = B*N = 25088
//   Q = (xt @ Wq^T + bq) * D^-0.5 ; KV = xt @ Wkv^T + bkv
//   attn = mix(softmax, relu^2)(q k^T + rpb) ; o = attn v ; y = o @ Wproj^T + b
// ---------------------------------------------------------------------------
#define BD   512
#define CD   1024
#define NTOK 49
#define HH   8
#define DD   128
#define MM   (BD * NTOK)          // 25088
#define KK   1024

// Device scratch (allocation-free rule: __device__ globals)
__device__ __half g_xt  [MM * CD];          // (M, C)    xt, fp16
__device__ __half g_qkvh[MM * 3 * CD];      // (M, 3C)   [q | k | v] fp16
__device__ __half g_o1  [MM * CD];          // (M, C)    attn out, fp16
__device__ __half g_wqkv[3 * CD * KK];      // [Wq ; Wkv] fp16
__device__ float  g_bqkv[3 * CD];           // [bq ; bkv]
__device__ __half g_wp  [CD * KK];          // Wproj fp16

// ---------------------------------------------------------------------------
// PTX helpers
// ---------------------------------------------------------------------------
__device__ __forceinline__ void cpa16(unsigned dst, const void* src) {
    asm volatile("cp.async.cg.shared.global [%0], [%1], 16;\n" :: "r"(dst), "l"(src));
}
__device__ __forceinline__ void cpa_commit() {
    asm volatile("cp.async.commit_group;\n");
}
__device__ __forceinline__ void cpa_wait1() {
    asm volatile("cp.async.wait_group 1;\n");
}
#define LDSM_X4(r0, r1, r2, r3, addr) \
    asm volatile("ldmatrix.sync.aligned.m8n8.x4.shared.b16 {%0,%1,%2,%3}, [%4];" \
                 : "=r"(r0), "=r"(r1), "=r"(r2), "=r"(r3) : "r"(addr))
#define LDSM_X4_T(r0, r1, r2, r3, addr) \
    asm volatile("ldmatrix.sync.aligned.m8n8.x4.trans.shared.b16 {%0,%1,%2,%3}, [%4];" \
                 : "=r"(r0), "=r"(r1), "=r"(r2), "=r"(r3) : "r"(addr))

__device__ __forceinline__ void mma16(float* c, const unsigned* a, const unsigned* b) {
    asm volatile(
        "mma.sync.aligned.m16n8k16.row.col.f32.f16.f16.f32 "
        "{%0,%1,%2,%3}, {%4,%5,%6,%7}, {%8,%9}, {%0,%1,%2,%3};"
        : "+f"(c[0]), "+f"(c[1]), "+f"(c[2]), "+f"(c[3])
        : "r"(a[0]), "r"(a[1]), "r"(a[2]), "r"(a[3]), "r"(b[0]), "r"(b[1]));
}

// ---------------------------------------------------------------------------
// Kernel 0: one-shot prep — all weights f32->f16 + bias concat
// ---------------------------------------------------------------------------
#define NQ  (CD * KK / 2)
#define NKV (2 * CD * KK / 2)
#define NP  (CD * KK / 2)
#define PREP_TOTAL (NQ + NKV + NP + 3 * CD)

__global__ __launch_bounds__(256) void prep_kernel(
    const float* __restrict__ Wq, const float* __restrict__ Wkv,
    const float* __restrict__ Wproj,
    const float* __restrict__ bq, const float* __restrict__ bkv)
{
    int i = blockIdx.x * 256 + threadIdx.x;
    if (i < NQ) {
        float2 v = ((const float2*)Wq)[i];
        ((__half2*)g_wqkv)[i] = __floats2half2_rn(v.x, v.y);
    } else if (i < NQ + NKV) {
        int j = i - NQ;
        float2 v = ((const float2*)Wkv)[j];
        ((__half2*)g_wqkv)[NQ + j] = __floats2half2_rn(v.x, v.y);
    } else if (i < NQ + NKV + NP) {
        int j = i - NQ - NKV;
        float2 v = ((const float2*)Wproj)[j];
        ((__half2*)g_wp)[j] = __floats2half2_rn(v.x, v.y);
    } else if (i < PREP_TOTAL) {
        int j = i - NQ - NKV - NP;
        g_bqkv[j] = (j < CD) ? bq[j] : bkv[j - CD];
    }
}

// ---------------------------------------------------------------------------
// Kernel 1: x (B, C, N) -> xt (M, C), fp16, coalesced half2 stores
// ---------------------------------------------------------------------------
__global__ __launch_bounds__(256) void transpose_in(const float* __restrict__ x) {
    __shared__ float t[NTOK][65];
    int b  = blockIdx.x;
    int c0 = blockIdx.y * 64;
    const float* xp = x + (size_t)b * CD * NTOK + (size_t)c0 * NTOK;
    for (int idx = threadIdx.x; idx < 64 * NTOK; idx += 256) {
        int c = idx / NTOK, n = idx - c * NTOK;
        t[n][c] = xp[c * NTOK + n];
    }
    __syncthreads();
    for (int idx = threadIdx.x; idx < NTOK * 32; idx += 256) {
        int n = idx >> 5, p = idx & 31;
        __half2 h = __floats2half2_rn(t[n][2 * p], t[n][2 * p + 1]);
        *(__half2*)&g_xt[(size_t)(b * NTOK + n) * CD + c0 + 2 * p] = h;
    }
}

// ---------------------------------------------------------------------------
// Kernel 2: fp16 GEMM (fp32 acc), tile 128x128x64, 3-stage cp.async,
//   8 warps (2x4), ldmatrix.x4, mma m16n8k16.
//   mode 0: Co  [row, colOff+col] = acc + bias  (fp32)
//   mode 1: y[b, col, n] = acc + bias           (fused output transpose)
//   mode 2: C16 [row, colOff+col] = acc + bias  (fp16 half2 stores)
// ---------------------------------------------------------------------------
#define BK 64
#define NKT (KK / BK)                // 16
#define TILE_B 16384                 // 128 rows * 128 B
#define STAGE_B (2 * TILE_B)
#define GEMM_SMEM (3 * STAGE_B)      // 98304

__global__ __launch_bounds__(256) void gemm_f16(
    const __half* __restrict__ A, const __half* __restrict__ W,
    const float* __restrict__ bias, float* __restrict__ Co,
    __half* __restrict__ C16, int ldc, int colOff, int mode)
{
    extern __shared__ __align__(128) unsigned char gsm[];
    const uint32_t smb = (uint32_t)__cvta_generic_to_shared(gsm);

    const int tid  = threadIdx.x;
    const int m0   = blockIdx.y * 128;
    const int n0   = blockIdx.x * 128;
    const int warp = tid >> 5, lane = tid & 31;
    const int wm = warp >> 2, wn = warp & 3;          // 2 x 4

    const __half* Ab = A + (size_t)m0 * KK;
    const __half* Wb = W + (size_t)n0 * KK;

    const int l7 = lane & 7;
    int rowA[4], rowB[2];
#pragma unroll
    for (int mi = 0; mi < 4; mi++)
        rowA[mi] = wm * 64 + mi * 16 + l7 + ((lane >> 3) & 1) * 8;
#pragma unroll
    for (int p = 0; p < 2; p++)
        rowB[p] = wn * 32 + p * 16 + l7 + (lane >> 4) * 8;
    const int gaof = lane >> 4;
    const int gbof = (lane >> 3) & 1;

    float acc[4][4][4];
#pragma unroll
    for (int mi = 0; mi < 4; mi++)
#pragma unroll
        for (int ni = 0; ni < 4; ni++)
#pragma unroll
            for (int q = 0; q < 4; q++) acc[mi][ni][q] = 0.f;

    auto fill = [&](int buf, int kt) {
        uint32_t baseA = smb + buf * STAGE_B;
        uint32_t baseB = baseA + TILE_B;
        int kof = kt * BK;
#pragma unroll
        for (int i = 0; i < 4; i++) {
            int u = i * 256 + tid;
            int row = u >> 3, g = u & 7;
            uint32_t sw = ((uint32_t)(g ^ (row & 7))) << 4;
            cpa16(baseA + row * 128 + sw, Ab + (size_t)row * KK + kof + g * 8);
            cpa16(baseB + row * 128 + sw, Wb + (size_t)row * KK + kof + g * 8);
        }
    };

    fill(0, 0); cpa_commit();
    fill(1, 1); cpa_commit();

    for (int kt = 0; kt < NKT; kt++) {
        int buf = kt % 3;
        cpa_wait1();
        __syncthreads();

        if (kt + 2 < NKT) fill((kt + 2) % 3, kt + 2);
        cpa_commit();

        uint32_t sA = smb + buf * STAGE_B;
        uint32_t sB = sA + TILE_B;

#pragma unroll
        for (int k16 = 0; k16 < 4; k16++) {
            unsigned af[4][4], bf[4][2];
            uint32_t sga = ((uint32_t)((k16 * 2 + gaof) ^ l7)) << 4;
            uint32_t sgb = ((uint32_t)((k16 * 2 + gbof) ^ l7)) << 4;
#pragma unroll
            for (int mi = 0; mi < 4; mi++)
                LDSM_X4(af[mi][0], af[mi][1], af[mi][2], af[mi][3],
                        sA + rowA[mi] * 128 + sga);
#pragma unroll
            for (int p = 0; p < 2; p++)
                LDSM_X4(bf[p * 2][0], bf[p * 2][1], bf[p * 2 + 1][0], bf[p * 2 + 1][1],
                        sB + rowB[p] * 128 + sgb);
#pragma unroll
            for (int mi = 0; mi < 4; mi++)
#pragma unroll
                for (int ni = 0; ni < 4; ni++)
                    mma16(acc[mi][ni], af[mi], bf[ni]);
        }
    }

    const int g4 = lane >> 2, t4 = lane & 3;
    if (mode == 0) {
#pragma unroll
        for (int mi = 0; mi < 4; mi++) {
#pragma unroll
            for (int ni = 0; ni < 4; ni++) {
                int row = m0 + wm * 64 + mi * 16 + g4;
                int col = n0 + wn * 32 + ni * 8 + t4 * 2;
                float b0 = bias[col], b1 = bias[col + 1];
                float2 v0 = { acc[mi][ni][0] + b0, acc[mi][ni][1] + b1 };
                float2 v1 = { acc[mi][ni][2] + b0, acc[mi][ni][3] + b1 };
                *(float2*)&Co[(size_t)row       * ldc + colOff + col] = v0;
                *(float2*)&Co[(size_t)(row + 8) * ldc + colOff + col] = v1;
            }
        }
    } else if (mode == 2) {
#pragma unroll
        for (int mi = 0; mi < 4; mi++) {
#pragma unroll
            for (int ni = 0; ni < 4; ni++) {
                int row = m0 + wm * 64 + mi * 16 + g4;
                int col = n0 + wn * 32 + ni * 8 + t4 * 2;
                float b0 = bias[col], b1 = bias[col + 1];
                *(__half2*)&C16[(size_t)row * ldc + colOff + col] =
                    __floats2half2_rn(acc[mi][ni][0] + b0, acc[mi][ni][1] + b1);
                *(__half2*)&C16[(size_t)(row + 8) * ldc + colOff + col] =
                    __floats2half2_rn(acc[mi][ni][2] + b0, acc[mi][ni][3] + b1);
            }
        }
    } else {
        // fused output transpose: stage (+bias) into smem [128][129], then
        // write y[b, col, n] with n-contiguous runs
        __syncthreads();                    // pipeline buffers now free
        float* st = (float*)gsm;
#pragma unroll
        for (int mi = 0; mi < 4; mi++) {
#pragma unroll
            for (int ni = 0; ni < 4; ni++) {
                int row = wm * 64 + mi * 16 + g4;
                int col = wn * 32 + ni * 8 + t4 * 2;
                float b0 = bias[n0 + col], b1 = bias[n0 + col + 1];
                st[row * 129 + col]           = acc[mi][ni][0] + b0;
                st[row * 129 + col + 1]       = acc[mi][ni][1] + b1;
                st[(row + 8) * 129 + col]     = acc[mi][ni][2] + b0;
                st[(row + 8) * 129 + col + 1] = acc[mi][ni][3] + b1;
            }
        }
        __syncthreads();
        for (int idx = tid; idx < 128 * 128; idx += 256) {
            int c = idx >> 7, r = idx & 127;
            int grow = m0 + r;
            int b = grow / NTOK, n = grow - b * NTOK;
            Co[(size_t)b * CD * NTOK + (size_t)(n0 + c) * NTOK + n] = st[r * 129 + c];
        }
    }
}

// ---------------------------------------------------------------------------
// Kernel 3: tensor-core windowed attention per (b, h). 256 threads, 4096 blocks.
//   Register-resident softmax (no fp32 S buffer), v via ldmatrix.trans.
//   smem 52.7KB -> 4 CTAs/SM.
// ---------------------------------------------------------------------------
#define AP 136            // halves per q/k/v row (272 B)
#define VP 72             // halves per attn row (144 B)
#define ATTN_TC_SMEM (3 * 64 * AP * 2 + 176 * 4 + 256 * 4)

__global__ __launch_bounds__(256) void attn_tc(const float* __restrict__ rpb_table,
                                               const float* __restrict__ w_mix)
{
    extern __shared__ __align__(16) unsigned char asmm[];
    __half* qs = (__half*)asmm;                 // 64 x AP ; later: attn (VP pitch)
    __half* ks = qs + 64 * AP;                  // 64 x AP ; later: O staging
    __half* vs = ks + 64 * AP;                  // 64 x AP (v rows, like k)
    float*  rp = (float*)(vs + 64 * AP);        // 176
    float*  red = rp + 176;                     // [max:128][sum:128]

    const int bh = blockIdx.x;
    const int b = bh >> 3, h = bh & 7;
    const int tid = threadIdx.x;
    const int warp = tid >> 5, lane = tid & 31;

    float wa = w_mix[0], wb = w_mix[1];
    float wmx = fmaxf(wa, wb);
    float ea = __expf(wa - wmx), eb = __expf(wb - wmx);
    float wden = 1.f / (ea + eb);
    float w0 = ea * wden, w1 = eb * wden;

    const float scale = 0.08838834764831845f;   // 128^-0.5
    size_t base = (size_t)(b * NTOK) * (3 * CD) + h * DD;

    // ---- load q, k, v (uint4; rows >= 49 zero-filled)
    const uint4 uz = {0u, 0u, 0u, 0u};
#pragma unroll
    for (int s = 0; s < 4; s++) {
        int idx = s * 256 + tid;                // 0..1023
        int row = idx >> 4, c = idx & 15;
        uint4 vq = uz, vk = uz, vv = uz;
        if (row < NTOK) {
            size_t g = base + (size_t)row * (3 * CD) + c * 8;
            vq = *(const uint4*)(g_qkvh + g);
            vk = *(const uint4*)(g_qkvh + g + CD);
            vv = *(const uint4*)(g_qkvh + g + 2 * CD);
        }
        *(uint4*)(qs + row * AP + c * 8) = vq;
        *(uint4*)(ks + row * AP + c * 8) = vk;
        *(uint4*)(vs + row * AP + c * 8) = vv;
    }
    for (int idx = tid; idx < 169; idx += 256) rp[idx] = rpb_table[idx * HH + h];
    __syncthreads();

    const uint32_t qb = (uint32_t)__cvta_generic_to_shared(qs);
    const uint32_t kb = (uint32_t)__cvta_generic_to_shared(ks);
    const uint32_t vb = (uint32_t)__cvta_generic_to_shared(vs);

    const int wm = warp >> 1, wn = warp & 1;    // 4 x 2
    const int l7 = lane & 7;
    const int rA  = wm * 16 + l7 + ((lane >> 3) & 1) * 8;
    const int gaof = lane >> 4, gbof = (lane >> 3) & 1;
    const int g4 = lane >> 2, t4 = lane & 3;

    // ---- S = q k^T  (M=64, N=64, K=128); warp tile 16 x 32
    float sc[4][4];
#pragma unroll
    for (int ni = 0; ni < 4; ni++)
#pragma unroll
        for (int q = 0; q < 4; q++) sc[ni][q] = 0.f;
    {
        const int rB0 = wn * 32 + l7 + (lane >> 4) * 8;
        const int rB1 = rB0 + 16;
#pragma unroll
        for (int k16 = 0; k16 < 8; k16++) {
            unsigned af[4], bf[4][2];
            LDSM_X4(af[0], af[1], af[2], af[3],
                    qb + rA * 272 + (k16 * 2 + gaof) * 16);
            LDSM_X4(bf[0][0], bf[0][1], bf[1][0], bf[1][1],
                    kb + rB0 * 272 + (k16 * 2 + gbof) * 16);
            LDSM_X4(bf[2][0], bf[2][1], bf[3][0], bf[3][1],
                    kb + rB1 * 272 + (k16 * 2 + gbof) * 16);
#pragma unroll
            for (int ni = 0; ni < 4; ni++) mma16(sc[ni], af, bf[ni]);
        }
    }

    // ---- register softmax + relu^2 mix
    const int r0 = wm * 16 + g4, r1 = r0 + 8;
    int r0e = (r0 < NTOK) ? r0 : 48;
    int r1e = (r1 < NTOK) ? r1 : 48;
    int ri0 = r0e / 7, ci0 = r0e - 7 * ri0;
    int ri1 = r1e / 7, ci1 = r1e - 7 * ri1;

    float x0[8], x1[8];
#pragma unroll
    for (int ni = 0; ni < 4; ni++) {
#pragma unroll
        for (int q2 = 0; q2 < 2; q2++) {
            int j = wn * 32 + ni * 8 + t4 * 2 + q2;
            int e = ni * 2 + q2;
            if (j < NTOK) {
                int rj = j / 7, cj = j - 7 * rj;
                x0[e] = sc[ni][q2]     * scale + rp[(ri0 - rj + 6) * 13 + (ci0 - cj + 6)];
                x1[e] = sc[ni][2 + q2] * scale + rp[(ri1 - rj + 6) * 13 + (ci1 - cj + 6)];
            } else {
                x0[e] = -1e30f;
                x1[e] = -1e30f;
            }
        }
    }

    float m0 = x0[0], m1 = x1[0];
#pragma unroll
    for (int e = 1; e < 8; e++) { m0 = fmaxf(m0, x0[e]); m1 = fmaxf(m1, x1[e]); }
    m0 = fmaxf(m0, __shfl_xor_sync(0xffffffffu, m0, 1));
    m0 = fmaxf(m0, __shfl_xor_sync(0xffffffffu, m0, 2));
    m1 = fmaxf(m1, __shfl_xor_sync(0xffffffffu, m1, 1));
    m1 = fmaxf(m1, __shfl_xor_sync(0xffffffffu, m1, 2));
    if (t4 == 0) { red[r0 * 2 + wn] = m0; red[r1 * 2 + wn] = m1; }
    __syncthreads();                 // also: qs now dead -> attn buffer
    m0 = fmaxf(red[r0 * 2], red[r0 * 2 + 1]);
    m1 = fmaxf(red[r1 * 2], red[r1 * 2 + 1]);

    float p0[8], p1[8];
    float s0 = 0.f, s1 = 0.f;
#pragma unroll
    for (int e = 0; e < 8; e++) {
        p0[e] = __expf(x0[e] - m0); s0 += p0[e];
        p1[e] = __expf(x1[e] - m1); s1 += p1[e];
    }
    s0 += __shfl_xor_sync(0xffffffffu, s0, 1);
    s0 += __shfl_xor_sync(0xffffffffu, s0, 2);
    s1 += __shfl_xor_sync(0xffffffffu, s1, 1);
    s1 += __shfl_xor_sync(0xffffffffu, s1, 2);
    if (t4 == 0) { red[128 + r0 * 2 + wn] = s0; red[128 + r1 * 2 + wn] = s1; }
    __syncthreads();
    float inv0 = 1.f / (red[128 + r0 * 2] + red[128 + r0 * 2 + 1]);
    float inv1 = 1.f / (red[128 + r1 * 2] + red[128 + r1 * 2 + 1]);

    __half* at = qs;                 // attn buffer, VP pitch
    const uint32_t ab = qb;
    float rm0 = (r0 < NTOK) ? 1.f : 0.f;
    float rm1 = (r1 < NTOK) ? 1.f : 0.f;
#pragma unroll
    for (int ni = 0; ni < 4; ni++) {
        int jb = wn * 32 + ni * 8 + t4 * 2;
        float u00 = fmaxf(x0[ni * 2], 0.f),     u01 = fmaxf(x0[ni * 2 + 1], 0.f);
        float u10 = fmaxf(x1[ni * 2], 0.f),     u11 = fmaxf(x1[ni * 2 + 1], 0.f);
        float a00 = rm0 * (w0 * p0[ni * 2] * inv0     + w1 * u00 * u00);
        float a01 = rm0 * (w0 * p0[ni * 2 + 1] * inv0 + w1 * u01 * u01);
        float a10 = rm1 * (w0 * p1[ni * 2] * inv1     + w1 * u10 * u10);
        float a11 = rm1 * (w0 * p1[ni * 2 + 1] * inv1 + w1 * u11 * u11);
        *(__half2*)(at + r0 * VP + jb) = __floats2half2_rn(a00, a01);
        *(__half2*)(at + r1 * VP + jb) = __floats2half2_rn(a10, a11);
    }
    __syncthreads();

    // ---- O = attn @ v  (M=64, N=128, K=64); v B-fragments via ldmatrix.trans
    float oc[8][4];
#pragma unroll
    for (int ni = 0; ni < 8; ni++)
#pragma unroll
        for (int q = 0; q < 4; q++) oc[ni][q] = 0.f;

    const int vkrow = ((lane >> 3) & 1) * 8 + l7;     // k-row within 16
    const int vnoff = (lane >> 4) * 8;                // n sub-offset
#pragma unroll
    for (int k16 = 0; k16 < 4; k16++) {
        unsigned af[4], bf[8][2];
        LDSM_X4(af[0], af[1], af[2], af[3],
                ab + rA * 144 + (k16 * 2 + gaof) * 16);
#pragma unroll
        for (int p = 0; p < 4; p++) {
            int krow = k16 * 16 + vkrow;
            int ncol = wn * 64 + p * 16 + vnoff;
            LDSM_X4_T(bf[p * 2][0], bf[p * 2][1], bf[p * 2 + 1][0], bf[p * 2 + 1][1],
                      vb + krow * 272 + ncol * 2);
        }
#pragma unroll
        for (int ni = 0; ni < 8; ni++) mma16(oc[ni], af, bf[ni]);
    }
    __syncthreads();            // ks free; reuse as O staging

#pragma unroll
    for (int ni = 0; ni < 8; ni++) {
        int row = wm * 16 + g4;
        int col = wn * 64 + ni * 8 + t4 * 2;
        ks[row * AP + col]           = __float2half_rn(oc[ni][0]);
        ks[row * AP + col + 1]       = __float2half_rn(oc[ni][1]);
        ks[(row + 8) * AP + col]     = __float2half_rn(oc[ni][2]);
        ks[(row + 8) * AP + col + 1] = __float2half_rn(oc[ni][3]);
    }
    __syncthreads();
    for (int idx = tid; idx < NTOK * 16; idx += 256) {
        int i = idx >> 4, c4 = idx & 15;
        uint4 v = *(uint4*)(ks + i * AP + c4 * 8);
        *(uint4*)(&g_o1[(size_t)(b * NTOK + i) * CD + h * DD + c4 * 8]) = v;
    }
}

// ---------------------------------------------------------------------------
// Launch
// ---------------------------------------------------------------------------
extern "C" void kernel_launch(void* const* d_in, const int* in_sizes, int n_in,
                              void* d_out, int out_size)
{
    const float* x     = (const float*)d_in[0];
    const float* Wq    = (const float*)d_in[1];
    const float* bq    = (const float*)d_in[2];
    const float* Wkv   = (const float*)d_in[3];
    const float* bkv   = (const float*)d_in[4];
    const float* rpb   = (const float*)d_in[5];
    const float* wmix  = (const float*)d_in[6];
    const float* Wproj = (const float*)d_in[7];
    const float* bproj = (const float*)d_in[8];
    float* y = (float*)d_out;

    void *p_xt, *p_qkvh, *p_o1, *p_wqkv, *p_bqkv, *p_wp;
    cudaGetSymbolAddress(&p_xt,   g_xt);
    cudaGetSymbolAddress(&p_qkvh, g_qkvh);
    cudaGetSymbolAddress(&p_o1,   g_o1);
    cudaGetSymbolAddress(&p_wqkv, g_wqkv);
    cudaGetSymbolAddress(&p_bqkv, g_bqkv);
    cudaGetSymbolAddress(&p_wp,   g_wp);

    cudaFuncSetAttribute(attn_tc, cudaFuncAttributeMaxDynamicSharedMemorySize,
                         ATTN_TC_SMEM);
    cudaFuncSetAttribute(gemm_f16, cudaFuncAttributeMaxDynamicSharedMemorySize,
                         GEMM_SMEM);

    // prep (weights fp16 + bias concat, one launch) + input transpose
    prep_kernel<<<(PREP_TOTAL + 255) / 256, 256>>>(Wq, Wkv, Wproj, bq, bkv);
    transpose_in<<<dim3(BD, CD / 64), 256>>>(x);

    // fused QKV GEMM: N = 3072, fp16 output
    gemm_f16<<<dim3(3 * CD / 128, MM / 128), 256, GEMM_SMEM>>>(
        (const __half*)p_xt, (const __half*)p_wqkv, (const float*)p_bqkv,
        nullptr, (__half*)p_qkvh, 3 * CD, 0, 2);

    attn_tc<<<BD * HH, 256, ATTN_TC_SMEM>>>(rpb, wmix);

    // proj GEMM with fused output transpose: writes y (B, C, 7, 7) directly
    gemm_f16<<<dim3(CD / 128, MM / 128), 256, GEMM_SMEM>>>(
        (const __half*)p_o1, (const __half*)p_wp, bproj, y, nullptr, 0, 0, 1);
}

// round 15
// speedup vs baseline: 2.9135x; 1.0210x over previous
#include <cuda_runtime.h>
#include <cuda_fp16.h>
#include <math.h>
#include <cstdint>

// ---------------------------------------------------------------------------
//   x: (B=512, C=1024, 7, 7) -> N = 49 tokens/window, M = B*N = 25088
//   Q = (xt @ Wq^T + bq) * D^-0.5 ; KV = xt @ Wkv^T + bkv
//   attn = mix(softmax, relu^2)(q k^T + rpb) ; o = attn v ; y = o @ Wproj^T + b
// ---------------------------------------------------------------------------
#define BD   512
#define CD   1024
#define NTOK 49
#define HH   8
#define DD   128
#define MM   (BD * NTOK)          // 25088
#define KK   1024

// Device scratch (allocation-free rule: __device__ globals)
__device__ __half g_xt  [MM * CD];          // (M, C)    xt, fp16
__device__ __half g_qkvh[MM * 3 * CD];      // (M, 3C)   [q | k | v] fp16
__device__ __half g_o1  [MM * CD];          // (M, C)    attn out, fp16
__device__ __half g_wqkv[3 * CD * KK];      // [Wq ; Wkv] fp16
__device__ float  g_bqkv[3 * CD];           // [bq ; bkv]
__device__ __half g_wp  [CD * KK];          // Wproj fp16

// ---------------------------------------------------------------------------
// PTX helpers
// ---------------------------------------------------------------------------
__device__ __forceinline__ void cpa16(unsigned dst, const void* src) {
    asm volatile("cp.async.cg.shared.global [%0], [%1], 16;\n" :: "r"(dst), "l"(src));
}
__device__ __forceinline__ void cpa_commit() {
    asm volatile("cp.async.commit_group;\n");
}
__device__ __forceinline__ void cpa_wait1() {
    asm volatile("cp.async.wait_group 1;\n");
}
__device__ __forceinline__ void cpa_wait0() {
    asm volatile("cp.async.wait_group 0;\n");
}
#define LDSM_X4(r0, r1, r2, r3, addr) \
    asm volatile("ldmatrix.sync.aligned.m8n8.x4.shared.b16 {%0,%1,%2,%3}, [%4];" \
                 : "=r"(r0), "=r"(r1), "=r"(r2), "=r"(r3) : "r"(addr))
#define LDSM_X4_T(r0, r1, r2, r3, addr) \
    asm volatile("ldmatrix.sync.aligned.m8n8.x4.trans.shared.b16 {%0,%1,%2,%3}, [%4];" \
                 : "=r"(r0), "=r"(r1), "=r"(r2), "=r"(r3) : "r"(addr))

__device__ __forceinline__ void mma16(float* c, const unsigned* a, const unsigned* b) {
    asm volatile(
        "mma.sync.aligned.m16n8k16.row.col.f32.f16.f16.f32 "
        "{%0,%1,%2,%3}, {%4,%5,%6,%7}, {%8,%9}, {%0,%1,%2,%3};"
        : "+f"(c[0]), "+f"(c[1]), "+f"(c[2]), "+f"(c[3])
        : "r"(a[0]), "r"(a[1]), "r"(a[2]), "r"(a[3]), "r"(b[0]), "r"(b[1]));
}

// ---------------------------------------------------------------------------
// Kernel 0: fused prep — weights f32->f16 + bias concat + x transpose.
//   blocks [0, PREP_BLKS): weight/bias conversion (1-D)
//   blocks [PREP_BLKS, PREP_BLKS + BD*16): x (B,C,N) -> xt (M,C) fp16
// ---------------------------------------------------------------------------
#define NQ  (CD * KK / 2)
#define NKV (2 * CD * KK / 2)
#define NP  (CD * KK / 2)
#define PREP_TOTAL (NQ + NKV + NP + 3 * CD)
#define PREP_BLKS  ((PREP_TOTAL + 255) / 256)
#define TRANS_BLKS (BD * (CD / 64))
#define FUSED_BLKS (PREP_BLKS + TRANS_BLKS)

__global__ __launch_bounds__(256) void fused_prep(
    const float* __restrict__ Wq, const float* __restrict__ Wkv,
    const float* __restrict__ Wproj,
    const float* __restrict__ bq, const float* __restrict__ bkv,
    const float* __restrict__ x)
{
    if (blockIdx.x < PREP_BLKS) {
        int i = blockIdx.x * 256 + threadIdx.x;
        if (i < NQ) {
            float2 v = ((const float2*)Wq)[i];
            ((__half2*)g_wqkv)[i] = __floats2half2_rn(v.x, v.y);
        } else if (i < NQ + NKV) {
            int j = i - NQ;
            float2 v = ((const float2*)Wkv)[j];
            ((__half2*)g_wqkv)[NQ + j] = __floats2half2_rn(v.x, v.y);
        } else if (i < NQ + NKV + NP) {
            int j = i - NQ - NKV;
            float2 v = ((const float2*)Wproj)[j];
            ((__half2*)g_wp)[j] = __floats2half2_rn(v.x, v.y);
        } else if (i < PREP_TOTAL) {
            int j = i - NQ - NKV - NP;
            g_bqkv[j] = (j < CD) ? bq[j] : bkv[j - CD];
        }
    } else {
        __shared__ float t[NTOK][65];
        int bid = blockIdx.x - PREP_BLKS;
        int b  = bid >> 4;
        int c0 = (bid & 15) * 64;
        const float* xp = x + (size_t)b * CD * NTOK + (size_t)c0 * NTOK;
        for (int idx = threadIdx.x; idx < 64 * NTOK; idx += 256) {
            int c = idx / NTOK, n = idx - c * NTOK;
            t[n][c] = xp[c * NTOK + n];
        }
        __syncthreads();
        for (int idx = threadIdx.x; idx < NTOK * 32; idx += 256) {
            int n = idx >> 5, p = idx & 31;
            __half2 h = __floats2half2_rn(t[n][2 * p], t[n][2 * p + 1]);
            *(__half2*)&g_xt[(size_t)(b * NTOK + n) * CD + c0 + 2 * p] = h;
        }
    }
}

// ---------------------------------------------------------------------------
// Kernel 2: fp16 GEMM (fp32 acc), tile 128x128x64, 3-stage cp.async,
//   8 warps (2x4), ldmatrix.x4, mma m16n8k16.
//   mode 1: y[b, col, n] = acc + bias           (fused output transpose)
//   mode 2: C16 [row, colOff+col] = acc + bias  (fp16 half2 stores)
// ---------------------------------------------------------------------------
#define BK 64
#define NKT (KK / BK)                // 16
#define TILE_B 16384                 // 128 rows * 128 B
#define STAGE_B (2 * TILE_B)
#define GEMM_SMEM (3 * STAGE_B)      // 98304

__global__ __launch_bounds__(256) void gemm_f16(
    const __half* __restrict__ A, const __half* __restrict__ W,
    const float* __restrict__ bias, float* __restrict__ Co,
    __half* __restrict__ C16, int ldc, int colOff, int mode)
{
    extern __shared__ __align__(128) unsigned char gsm[];
    const uint32_t smb = (uint32_t)__cvta_generic_to_shared(gsm);

    const int tid  = threadIdx.x;
    const int m0   = blockIdx.y * 128;
    const int n0   = blockIdx.x * 128;
    const int warp = tid >> 5, lane = tid & 31;
    const int wm = warp >> 2, wn = warp & 3;          // 2 x 4

    const __half* Ab = A + (size_t)m0 * KK;
    const __half* Wb = W + (size_t)n0 * KK;

    const int l7 = lane & 7;
    int rowA[4], rowB[2];
#pragma unroll
    for (int mi = 0; mi < 4; mi++)
        rowA[mi] = wm * 64 + mi * 16 + l7 + ((lane >> 3) & 1) * 8;
#pragma unroll
    for (int p = 0; p < 2; p++)
        rowB[p] = wn * 32 + p * 16 + l7 + (lane >> 4) * 8;
    const int gaof = lane >> 4;
    const int gbof = (lane >> 3) & 1;

    float acc[4][4][4];
#pragma unroll
    for (int mi = 0; mi < 4; mi++)
#pragma unroll
        for (int ni = 0; ni < 4; ni++)
#pragma unroll
            for (int q = 0; q < 4; q++) acc[mi][ni][q] = 0.f;

    auto fill = [&](int buf, int kt) {
        uint32_t baseA = smb + buf * STAGE_B;
        uint32_t baseB = baseA + TILE_B;
        int kof = kt * BK;
#pragma unroll
        for (int i = 0; i < 4; i++) {
            int u = i * 256 + tid;
            int row = u >> 3, g = u & 7;
            uint32_t sw = ((uint32_t)(g ^ (row & 7))) << 4;
            cpa16(baseA + row * 128 + sw, Ab + (size_t)row * KK + kof + g * 8);
            cpa16(baseB + row * 128 + sw, Wb + (size_t)row * KK + kof + g * 8);
        }
    };

    fill(0, 0); cpa_commit();
    fill(1, 1); cpa_commit();

    for (int kt = 0; kt < NKT; kt++) {
        int buf = kt % 3;
        cpa_wait1();
        __syncthreads();

        if (kt + 2 < NKT) fill((kt + 2) % 3, kt + 2);
        cpa_commit();

        uint32_t sA = smb + buf * STAGE_B;
        uint32_t sB = sA + TILE_B;

#pragma unroll
        for (int k16 = 0; k16 < 4; k16++) {
            unsigned af[4][4], bf[4][2];
            uint32_t sga = ((uint32_t)((k16 * 2 + gaof) ^ l7)) << 4;
            uint32_t sgb = ((uint32_t)((k16 * 2 + gbof) ^ l7)) << 4;
#pragma unroll
            for (int mi = 0; mi < 4; mi++)
                LDSM_X4(af[mi][0], af[mi][1], af[mi][2], af[mi][3],
                        sA + rowA[mi] * 128 + sga);
#pragma unroll
            for (int p = 0; p < 2; p++)
                LDSM_X4(bf[p * 2][0], bf[p * 2][1], bf[p * 2 + 1][0], bf[p * 2 + 1][1],
                        sB + rowB[p] * 128 + sgb);
#pragma unroll
            for (int mi = 0; mi < 4; mi++)
#pragma unroll
                for (int ni = 0; ni < 4; ni++)
                    mma16(acc[mi][ni], af[mi], bf[ni]);
        }
    }

    const int g4 = lane >> 2, t4 = lane & 3;
    if (mode == 2) {
#pragma unroll
        for (int mi = 0; mi < 4; mi++) {
#pragma unroll
            for (int ni = 0; ni < 4; ni++) {
                int row = m0 + wm * 64 + mi * 16 + g4;
                int col = n0 + wn * 32 + ni * 8 + t4 * 2;
                float b0 = bias[col], b1 = bias[col + 1];
                *(__half2*)&C16[(size_t)row * ldc + colOff + col] =
                    __floats2half2_rn(acc[mi][ni][0] + b0, acc[mi][ni][1] + b1);
                *(__half2*)&C16[(size_t)(row + 8) * ldc + colOff + col] =
                    __floats2half2_rn(acc[mi][ni][2] + b0, acc[mi][ni][3] + b1);
            }
        }
    } else {
        // fused output transpose: stage (+bias) into smem [128][129], then
        // write y[b, col, n] with n-contiguous runs
        __syncthreads();                    // pipeline buffers now free
        float* st = (float*)gsm;
#pragma unroll
        for (int mi = 0; mi < 4; mi++) {
#pragma unroll
            for (int ni = 0; ni < 4; ni++) {
                int row = wm * 64 + mi * 16 + g4;
                int col = wn * 32 + ni * 8 + t4 * 2;
                float b0 = bias[n0 + col], b1 = bias[n0 + col + 1];
                st[row * 129 + col]           = acc[mi][ni][0] + b0;
                st[row * 129 + col + 1]       = acc[mi][ni][1] + b1;
                st[(row + 8) * 129 + col]     = acc[mi][ni][2] + b0;
                st[(row + 8) * 129 + col + 1] = acc[mi][ni][3] + b1;
            }
        }
        __syncthreads();
        for (int idx = tid; idx < 128 * 128; idx += 256) {
            int c = idx >> 7, r = idx & 127;
            int grow = m0 + r;
            int b = grow / NTOK, n = grow - b * NTOK;
            Co[(size_t)b * CD * NTOK + (size_t)(n0 + c) * NTOK + n] = st[r * 129 + c];
        }
    }
}

// ---------------------------------------------------------------------------
// Kernel 3: tensor-core windowed attention per (b, h). 256 threads, 4096 blocks.
//   Register-resident softmax, v via ldmatrix.trans, cp.async loads.
//   smem 52.7KB -> 4 CTAs/SM.
// ---------------------------------------------------------------------------
#define AP 136            // halves per q/k/v row (272 B)
#define VP 72             // halves per attn row (144 B)
#define ATTN_TC_SMEM (3 * 64 * AP * 2 + 176 * 4 + 256 * 4)

__global__ __launch_bounds__(256) void attn_tc(const float* __restrict__ rpb_table,
                                               const float* __restrict__ w_mix)
{
    extern __shared__ __align__(16) unsigned char asmm[];
    __half* qs = (__half*)asmm;                 // 64 x AP ; later: attn (VP pitch)
    __half* ks = qs + 64 * AP;                  // 64 x AP ; later: O staging
    __half* vs = ks + 64 * AP;                  // 64 x AP (v rows, like k)
    float*  rp = (float*)(vs + 64 * AP);        // 176
    float*  red = rp + 176;                     // [max:128][sum:128]

    const int bh = blockIdx.x;
    const int b = bh >> 3, h = bh & 7;
    const int tid = threadIdx.x;
    const int warp = tid >> 5, lane = tid & 31;

    float wa = w_mix[0], wb = w_mix[1];
    float wmx = fmaxf(wa, wb);
    float ea = __expf(wa - wmx), eb = __expf(wb - wmx);
    float wden = 1.f / (ea + eb);
    float w0 = ea * wden, w1 = eb * wden;

    const float scale = 0.08838834764831845f;   // 128^-0.5
    size_t base = (size_t)(b * NTOK) * (3 * CD) + h * DD;

    const uint32_t qb = (uint32_t)__cvta_generic_to_shared(qs);
    const uint32_t kb = (uint32_t)__cvta_generic_to_shared(ks);
    const uint32_t vb = (uint32_t)__cvta_generic_to_shared(vs);

    // ---- loads: cp.async for rows < 49; zero-fill pads via STS
    const uint4 uz = {0u, 0u, 0u, 0u};
#pragma unroll
    for (int s = 0; s < 4; s++) {
        int idx = s * 256 + tid;                // 0..1023
        int row = idx >> 4, c = idx & 15;
        uint32_t off = (uint32_t)(row * AP + c * 8) * 2;
        if (row < NTOK) {
            const __half* g = g_qkvh + base + (size_t)row * (3 * CD) + c * 8;
            cpa16(qb + off, g);
            cpa16(kb + off, g + CD);
            cpa16(vb + off, g + 2 * CD);
        } else {
            *(uint4*)(qs + row * AP + c * 8) = uz;
            *(uint4*)(ks + row * AP + c * 8) = uz;
            *(uint4*)(vs + row * AP + c * 8) = uz;
        }
    }
    cpa_commit();
    for (int idx = tid; idx < 169; idx += 256) rp[idx] = rpb_table[idx * HH + h];
    cpa_wait0();
    __syncthreads();

    const int wm = warp >> 1, wn = warp & 1;    // 4 x 2
    const int l7 = lane & 7;
    const int rA  = wm * 16 + l7 + ((lane >> 3) & 1) * 8;
    const int gaof = lane >> 4, gbof = (lane >> 3) & 1;
    const int g4 = lane >> 2, t4 = lane & 3;

    // ---- S = q k^T  (M=64, N=64, K=128); warp tile 16 x 32
    float sc[4][4];
#pragma unroll
    for (int ni = 0; ni < 4; ni++)
#pragma unroll
        for (int q = 0; q < 4; q++) sc[ni][q] = 0.f;
    {
        const int rB0 = wn * 32 + l7 + (lane >> 4) * 8;
        const int rB1 = rB0 + 16;
#pragma unroll
        for (int k16 = 0; k16 < 8; k16++) {
            unsigned af[4], bf[4][2];
            LDSM_X4(af[0], af[1], af[2], af[3],
                    qb + rA * 272 + (k16 * 2 + gaof) * 16);
            LDSM_X4(bf[0][0], bf[0][1], bf[1][0], bf[1][1],
                    kb + rB0 * 272 + (k16 * 2 + gbof) * 16);
            LDSM_X4(bf[2][0], bf[2][1], bf[3][0], bf[3][1],
                    kb + rB1 * 272 + (k16 * 2 + gbof) * 16);
#pragma unroll
            for (int ni = 0; ni < 4; ni++) mma16(sc[ni], af, bf[ni]);
        }
    }

    // ---- register softmax + relu^2 mix
    const int r0 = wm * 16 + g4, r1 = r0 + 8;
    int r0e = (r0 < NTOK) ? r0 : 48;
    int r1e = (r1 < NTOK) ? r1 : 48;
    int ri0 = r0e / 7, ci0 = r0e - 7 * ri0;
    int ri1 = r1e / 7, ci1 = r1e - 7 * ri1;

    float x0[8], x1[8];
#pragma unroll
    for (int ni = 0; ni < 4; ni++) {
#pragma unroll
        for (int q2 = 0; q2 < 2; q2++) {
            int j = wn * 32 + ni * 8 + t4 * 2 + q2;
            int e = ni * 2 + q2;
            if (j < NTOK) {
                int rj = j / 7, cj = j - 7 * rj;
                x0[e] = sc[ni][q2]     * scale + rp[(ri0 - rj + 6) * 13 + (ci0 - cj + 6)];
                x1[e] = sc[ni][2 + q2] * scale + rp[(ri1 - rj + 6) * 13 + (ci1 - cj + 6)];
            } else {
                x0[e] = -1e30f;
                x1[e] = -1e30f;
            }
        }
    }

    float m0 = x0[0], m1 = x1[0];
#pragma unroll
    for (int e = 1; e < 8; e++) { m0 = fmaxf(m0, x0[e]); m1 = fmaxf(m1, x1[e]); }
    m0 = fmaxf(m0, __shfl_xor_sync(0xffffffffu, m0, 1));
    m0 = fmaxf(m0, __shfl_xor_sync(0xffffffffu, m0, 2));
    m1 = fmaxf(m1, __shfl_xor_sync(0xffffffffu, m1, 1));
    m1 = fmaxf(m1, __shfl_xor_sync(0xffffffffu, m1, 2));
    if (t4 == 0) { red[r0 * 2 + wn] = m0; red[r1 * 2 + wn] = m1; }
    __syncthreads();                 // also: qs now dead -> attn buffer
    m0 = fmaxf(red[r0 * 2], red[r0 * 2 + 1]);
    m1 = fmaxf(red[r1 * 2], red[r1 * 2 + 1]);

    float p0[8], p1[8];
    float s0 = 0.f, s1 = 0.f;
#pragma unroll
    for (int e = 0; e < 8; e++) {
        p0[e] = __expf(x0[e] - m0); s0 += p0[e];
        p1[e] = __expf(x1[e] - m1); s1 += p1[e];
    }
    s0 += __shfl_xor_sync(0xffffffffu, s0, 1);
    s0 += __shfl_xor_sync(0xffffffffu, s0, 2);
    s1 += __shfl_xor_sync(0xffffffffu, s1, 1);
    s1 += __shfl_xor_sync(0xffffffffu, s1, 2);
    if (t4 == 0) { red[128 + r0 * 2 + wn] = s0; red[128 + r1 * 2 + wn] = s1; }
    __syncthreads();
    float inv0 = 1.f / (red[128 + r0 * 2] + red[128 + r0 * 2 + 1]);
    float inv1 = 1.f / (red[128 + r1 * 2] + red[128 + r1 * 2 + 1]);

    __half* at = qs;                 // attn buffer, VP pitch
    const uint32_t ab = qb;
    float rm0 = (r0 < NTOK) ? 1.f : 0.f;
    float rm1 = (r1 < NTOK) ? 1.f : 0.f;
#pragma unroll
    for (int ni = 0; ni < 4; ni++) {
        int jb = wn * 32 + ni * 8 + t4 * 2;
        float u00 = fmaxf(x0[ni * 2], 0.f),     u01 = fmaxf(x0[ni * 2 + 1], 0.f);
        float u10 = fmaxf(x1[ni * 2], 0.f),     u11 = fmaxf(x1[ni * 2 + 1], 0.f);
        float a00 = rm0 * (w0 * p0[ni * 2] * inv0     + w1 * u00 * u00);
        float a01 = rm0 * (w0 * p0[ni * 2 + 1] * inv0 + w1 * u01 * u01);
        float a10 = rm1 * (w0 * p1[ni * 2] * inv1     + w1 * u10 * u10);
        float a11 = rm1 * (w0 * p1[ni * 2 + 1] * inv1 + w1 * u11 * u11);
        *(__half2*)(at + r0 * VP + jb) = __floats2half2_rn(a00, a01);
        *(__half2*)(at + r1 * VP + jb) = __floats2half2_rn(a10, a11);
    }
    __syncthreads();

    // ---- O = attn @ v  (M=64, N=128, K=64); v B-fragments via ldmatrix.trans
    float oc[8][4];
#pragma unroll
    for (int ni = 0; ni < 8; ni++)
#pragma unroll
        for (int q = 0; q < 4; q++) oc[ni][q] = 0.f;

    const int vkrow = ((lane >> 3) & 1) * 8 + l7;     // k-row within 16
    const int vnoff = (lane >> 4) * 8;                // n sub-offset
#pragma unroll
    for (int k16 = 0; k16 < 4; k16++) {
        unsigned af[4], bf[8][2];
        LDSM_X4(af[0], af[1], af[2], af[3],
                ab + rA * 144 + (k16 * 2 + gaof) * 16);
#pragma unroll
        for (int p = 0; p < 4; p++) {
            int krow = k16 * 16 + vkrow;
            int ncol = wn * 64 + p * 16 + vnoff;
            LDSM_X4_T(bf[p * 2][0], bf[p * 2][1], bf[p * 2 + 1][0], bf[p * 2 + 1][1],
                      vb + krow * 272 + ncol * 2);
        }
#pragma unroll
        for (int ni = 0; ni < 8; ni++) mma16(oc[ni], af, bf[ni]);
    }
    __syncthreads();            // ks free; reuse as O staging

#pragma unroll
    for (int ni = 0; ni < 8; ni++) {
        int row = wm * 16 + g4;
        int col = wn * 64 + ni * 8 + t4 * 2;
        ks[row * AP + col]           = __float2half_rn(oc[ni][0]);
        ks[row * AP + col + 1]       = __float2half_rn(oc[ni][1]);
        ks[(row + 8) * AP + col]     = __float2half_rn(oc[ni][2]);
        ks[(row + 8) * AP + col + 1] = __float2half_rn(oc[ni][3]);
    }
    __syncthreads();
    for (int idx = tid; idx < NTOK * 16; idx += 256) {
        int i = idx >> 4, c4 = idx & 15;
        uint4 v = *(uint4*)(ks + i * AP + c4 * 8);
        *(uint4*)(&g_o1[(size_t)(b * NTOK + i) * CD + h * DD + c4 * 8]) = v;
    }
}

// ---------------------------------------------------------------------------
// Launch
// ---------------------------------------------------------------------------
extern "C" void kernel_launch(void* const* d_in, const int* in_sizes, int n_in,
                              void* d_out, int out_size)
{
    const float* x     = (const float*)d_in[0];
    const float* Wq    = (const float*)d_in[1];
    const float* bq    = (const float*)d_in[2];
    const float* Wkv   = (const float*)d_in[3];
    const float* bkv   = (const float*)d_in[4];
    const float* rpb   = (const float*)d_in[5];
    const float* wmix  = (const float*)d_in[6];
    const float* Wproj = (const float*)d_in[7];
    const float* bproj = (const float*)d_in[8];
    float* y = (float*)d_out;

    void *p_xt, *p_qkvh, *p_o1, *p_wqkv, *p_bqkv, *p_wp;
    cudaGetSymbolAddress(&p_xt,   g_xt);
    cudaGetSymbolAddress(&p_qkvh, g_qkvh);
    cudaGetSymbolAddress(&p_o1,   g_o1);
    cudaGetSymbolAddress(&p_wqkv, g_wqkv);
    cudaGetSymbolAddress(&p_bqkv, g_bqkv);
    cudaGetSymbolAddress(&p_wp,   g_wp);

    cudaFuncSetAttribute(attn_tc, cudaFuncAttributeMaxDynamicSharedMemorySize,
                         ATTN_TC_SMEM);
    cudaFuncSetAttribute(gemm_f16, cudaFuncAttributeMaxDynamicSharedMemorySize,
                         GEMM_SMEM);

    // fused prep: weights fp16 + bias concat + x transpose, one launch
    fused_prep<<<FUSED_BLKS, 256>>>(Wq, Wkv, Wproj, bq, bkv, x);

    // fused QKV GEMM: N = 3072, fp16 output
    gemm_f16<<<dim3(3 * CD / 128, MM / 128), 256, GEMM_SMEM>>>(
        (const __half*)p_xt, (const __half*)p_wqkv, (const float*)p_bqkv,
        nullptr, (__half*)p_qkvh, 3 * CD, 0, 2);

    attn_tc<<<BD * HH, 256, ATTN_TC_SMEM>>>(rpb, wmix);

    // proj GEMM with fused output transpose: writes y (B, C, 7, 7) directly
    gemm_f16<<<dim3(CD / 128, MM / 128), 256, GEMM_SMEM>>>(
        (const __half*)p_o1, (const __half*)p_wp, bproj, y, nullptr, 0, 0, 1);
}